// round 14
// baseline (speedup 1.0000x reference)
#include <cuda_runtime.h>
#include <cuda_bf16.h>
#include <cuda_fp16.h>
#include <cstdint>

#define NN 32000
#define EE 512000
#define ET (EE + NN)
#define DD 128
#define HH 4
#define EAD 16

typedef __nv_bfloat16 bf16;

// ================= scratch =================
__device__ int   g_is64;
__device__ int   g_deg[NN];
__device__ int   g_off[NN + 1];
__device__ int   g_cur[NN];
__device__ int   g_csrc[ET];

__device__ __half g_xh [(size_t)NN * 128];
__device__ __half g_h2h[(size_t)NN * 128];
__device__ __half g_PQh[(size_t)NN * 256];
__device__ float g_att1s[NN * 4];
__device__ float g_att1d[NN * 4];
__device__ float g_att2s[NN];
__device__ float g_att2d[NN];
__device__ float g_bePQ[256];
__device__ float g_va[8 * 128];

__device__ bf16  g_Zp [(size_t)NN * 1024];
__device__ bf16  g_e1p[(size_t)NN * 1024];
__device__ bf16  g_W1t  [512 * 256];
__device__ bf16  g_W2t  [128 * 1024];
__device__ bf16  g_Wo1t [128 * 256];
__device__ bf16  g_Wo2t [128 * 256];
__device__ bf16  g_WePQt[256 * 256];

// ================= helpers =================
__device__ __forceinline__ float lrelu02(float a) { return a > 0.f ? a : 0.2f * a; }
__device__ __forceinline__ float eluf(float v)    { return v > 0.f ? v : expm1f(v); }
__device__ __forceinline__ int idx_at(const void* ei, long pos, int is64) {
    if (is64) return (int)((const long long*)ei)[pos];
    return ((const int*)ei)[pos];
}
__device__ __forceinline__ void split_bf16(float v, bf16& h, bf16& l) {
    h = __float2bfloat16(v);
    l = __float2bfloat16(v - __bfloat162float(h));
}
__device__ __forceinline__ uint32_t smem_u32(const void* p) {
    uint32_t a;
    asm("{ .reg .u64 t; cvta.to.shared.u64 t, %1; cvt.u32.u64 %0, t; }" : "=r"(a) : "l"(p));
    return a;
}
__device__ __forceinline__ void cp_async16(uint32_t saddr, const void* g) {
    asm volatile("cp.async.cg.shared.global [%0], [%1], 16;" :: "r"(saddr), "l"(g));
}
__device__ __forceinline__ void mma_bf16(float* c, const uint32_t* a, const uint32_t* b) {
    asm volatile(
        "mma.sync.aligned.m16n8k16.row.col.f32.bf16.bf16.f32 "
        "{%0,%1,%2,%3}, {%4,%5,%6,%7}, {%8,%9}, {%0,%1,%2,%3};"
        : "+f"(c[0]), "+f"(c[1]), "+f"(c[2]), "+f"(c[3])
        : "r"(a[0]), "r"(a[1]), "r"(a[2]), "r"(a[3]), "r"(b[0]), "r"(b[1]));
}
__device__ __forceinline__ void mma_f16(float* c, const uint32_t* a, const uint32_t* b) {
    asm volatile(
        "mma.sync.aligned.m16n8k16.row.col.f32.f16.f16.f32 "
        "{%0,%1,%2,%3}, {%4,%5,%6,%7}, {%8,%9}, {%0,%1,%2,%3};"
        : "+f"(c[0]), "+f"(c[1]), "+f"(c[2]), "+f"(c[3])
        : "r"(a[0]), "r"(a[1]), "r"(a[2]), "r"(a[3]), "r"(b[0]), "r"(b[1]));
}
__device__ __forceinline__ void ldm_x4(uint32_t* r, uint32_t addr) {
    asm volatile("ldmatrix.sync.aligned.m8n8.x4.shared.b16 {%0,%1,%2,%3}, [%4];"
                 : "=r"(r[0]), "=r"(r[1]), "=r"(r[2]), "=r"(r[3]) : "r"(addr));
}

// ================= prep: xh | convW | init | va =================
__device__ __forceinline__ void conv_emit(const float* W, bf16* Wt, int K, int N, int idx) {
    int n = idx / K;
    int k = idx - n * K;
    bf16 h, l;
    split_bf16(W[(size_t)k * N + n], h, l);
    bf16* row = Wt + (size_t)n * 2 * K;
    row[k] = h; row[K + k] = l;
}
__global__ void __launch_bounds__(256) k_prep(const float* x, const int* eiw,
                                              const float* W1, const float* W2,
                                              const float* Wo1, const float* Wo2,
                                              const float* We1, const float* be1,
                                              const float* as1, const float* ad1) {
    const int b = blockIdx.x, tid = threadIdx.x;
    if (b < 16000) {
        long i = (long)b * 256 + tid;
        g_xh[i] = __float2half(x[i]);
    } else if (b < 16770) {
        int i = (b - 16000) * 256 + tid;
        if (i < 65536)          conv_emit(W1,  g_W1t,  128, 512, i);
        else if (i < 131072)    conv_emit(W2,  g_W2t,  512, 128, i - 65536);
        else if (i < 147456)    conv_emit(Wo1, g_Wo1t, 128, 128, i - 131072);
        else if (i < 163840)    conv_emit(Wo2, g_Wo2t, 128, 128, i - 147456);
        else if (i < 180224)    conv_emit(We1, g_WePQt, 128, 128, i - 163840);
        else if (i < 196608)    conv_emit(We1 + 128 * 128, g_WePQt + 128 * 256, 128, 128, i - 180224);
        else if (i < 196864) {
            int j = i - 196608;
            g_bePQ[j] = (j < 128) ? be1[j] : 0.f;
        }
    } else if (b < 16895) {
        int i = (b - 16770) * 256 + tid;
        g_deg[i] = 0;
        if (b == 16770) {
            __shared__ int s_any;
            if (tid == 0) s_any = 0;
            __syncthreads();
            int any = 0;
            for (int j = tid; j < 1024; j += 256) any |= eiw[2 * j + 1];
            if (any) atomicOr(&s_any, 1);
            __syncthreads();
            if (tid == 0) g_is64 = (s_any == 0) ? 1 : 0;
        }
    } else {
        int v = (b - 16895) * 2 + (tid >> 7);
        int k = tid & 127;
        const float* a = (v < 4) ? (as1 + v * 128) : (ad1 + (v - 4) * 128);
        int hh = (v < 4) ? v : (v - 4);
        const float* wrow = W1 + (size_t)k * 512 + hh * 128;
        float s = 0.f;
#pragma unroll 4
        for (int c = 0; c < 128; c++) s += wrow[c] * a[c];
        g_va[v * 128 + k] = s;
    }
}

// ================= fused hist | attdot =================
__global__ void __launch_bounds__(256) k_histdot(const void* ei) {
    const int b = blockIdx.x, tid = threadIdx.x;
    if (b < 2125) {
        int is64 = g_is64;
        long e = (long)b * 256 + tid;
        int d = (e < EE) ? idx_at(ei, (long)EE + e, is64) : (int)(e - EE);
        atomicAdd(&g_deg[d], 1);
    } else {
        __shared__ float sva[1024];
        for (int i = tid; i < 1024; i += 256) sva[i] = g_va[i];
        __syncthreads();
        const int w = tid >> 5, lane = tid & 31;
        const int n = (b - 2125) * 8 + w;
        uint2 xv2 = *(const uint2*)&g_xh[(size_t)n * 128 + lane * 4];
        float2 xa = __half22float2(*(const __half2*)&xv2.x);
        float2 xb = __half22float2(*(const __half2*)&xv2.y);
        float dots[8];
#pragma unroll
        for (int v = 0; v < 8; v++) {
            float4 vv = *(const float4*)&sva[v * 128 + lane * 4];
            dots[v] = xa.x * vv.x + xa.y * vv.y + xb.x * vv.z + xb.y * vv.w;
        }
#pragma unroll
        for (int off = 16; off; off >>= 1)
#pragma unroll
            for (int v = 0; v < 8; v++)
                dots[v] += __shfl_xor_sync(0xffffffffu, dots[v], off);
        if (lane < 4)      g_att1s[n * 4 + lane] = dots[lane];
        else if (lane < 8) g_att1d[n * 4 + lane - 4] = dots[lane];
    }
}

__global__ void __launch_bounds__(1024) k_scan_all() {
    __shared__ int wsum[32];
    const int t = threadIdx.x, lane = t & 31, w = t >> 5;
    const int base = t * 32;
    int loc[32];
    int s = 0;
    if (base < NN) {
#pragma unroll
        for (int i = 0; i < 8; i++) {
            int4 v = *(const int4*)&g_deg[base + i * 4];
            loc[i * 4 + 0] = v.x; loc[i * 4 + 1] = v.y;
            loc[i * 4 + 2] = v.z; loc[i * 4 + 3] = v.w;
            s += v.x + v.y + v.z + v.w;
        }
    }
    int inc = s;
#pragma unroll
    for (int off = 1; off < 32; off <<= 1) {
        int xx = __shfl_up_sync(0xffffffffu, inc, off);
        if (lane >= off) inc += xx;
    }
    if (lane == 31) wsum[w] = inc;
    __syncthreads();
    if (w == 0) {
        int v = wsum[lane];
        int vi = v;
#pragma unroll
        for (int off = 1; off < 32; off <<= 1) {
            int xx = __shfl_up_sync(0xffffffffu, vi, off);
            if (lane >= off) vi += xx;
        }
        wsum[lane] = vi;
    }
    __syncthreads();
    const int warpoff = (w == 0) ? 0 : wsum[w - 1];
    int run = warpoff + inc - s;
    if (base < NN) {
#pragma unroll
        for (int i = 0; i < 32; i++) {
            g_off[base + i] = run;
            g_cur[base + i] = run;
            run += loc[i];
        }
    }
    if (t == 0) g_off[NN] = wsum[31];
}
__global__ void k_scatter(const void* ei) {
    int is64 = g_is64;
    long e = (long)blockIdx.x * 256 + threadIdx.x;
    int s, d;
    if (e < EE) {
        s = idx_at(ei, e, is64);
        d = idx_at(ei, (long)EE + e, is64);
    } else {
        s = d = (int)(e - EE);
    }
    int pos = atomicAdd(&g_cur[d], 1);
    g_csrc[pos] = s;
}

// ================= agg1x: warp-per-node =================
__global__ void __launch_bounds__(256) k_agg1x() {
    const int tid = threadIdx.x, wid = tid >> 5, lane = tid & 31;
    const int n = blockIdx.x * 8 + wid;
    const int beg = g_off[n], end = g_off[n + 1];

    const float4 ad = *(const float4*)&g_att1d[n * 4];
    float acc[4][4];
#pragma unroll
    for (int h = 0; h < 4; h++)
#pragma unroll
        for (int q = 0; q < 4; q++) acc[h][q] = 0.f;
    float den[4] = {0.f, 0.f, 0.f, 0.f};

    for (int c0 = beg; c0 < end; c0 += 32) {
        const int m = min(32, end - c0);
        int   sj = 0;
        float4 e4 = make_float4(0.f, 0.f, 0.f, 0.f);
        if (lane < m) {
            sj = g_csrc[c0 + lane];
            float4 as = *(const float4*)&g_att1s[sj * 4];
            e4.x = expf(lrelu02(as.x + ad.x));
            e4.y = expf(lrelu02(as.y + ad.y));
            e4.z = expf(lrelu02(as.z + ad.z));
            e4.w = expf(lrelu02(as.w + ad.w));
        }
        const int mr = (m + 7) & ~7;
        for (int j0 = 0; j0 < mr; j0 += 8) {
#pragma unroll
            for (int jj = 0; jj < 8; jj++) {
                const int j = j0 + jj;
                int   s  = __shfl_sync(0xffffffffu, sj,  j);
                float w0 = __shfl_sync(0xffffffffu, e4.x, j);
                float w1 = __shfl_sync(0xffffffffu, e4.y, j);
                float w2 = __shfl_sync(0xffffffffu, e4.z, j);
                float w3 = __shfl_sync(0xffffffffu, e4.w, j);
                uint2 xv = *(const uint2*)&g_xh[(size_t)s * 128 + lane * 4];
                float2 fa = __half22float2(*(const __half2*)&xv.x);
                float2 fb = __half22float2(*(const __half2*)&xv.y);
                den[0] += w0; den[1] += w1; den[2] += w2; den[3] += w3;
                acc[0][0] += w0 * fa.x; acc[0][1] += w0 * fa.y; acc[0][2] += w0 * fb.x; acc[0][3] += w0 * fb.y;
                acc[1][0] += w1 * fa.x; acc[1][1] += w1 * fa.y; acc[1][2] += w1 * fb.x; acc[1][3] += w1 * fb.y;
                acc[2][0] += w2 * fa.x; acc[2][1] += w2 * fa.y; acc[2][2] += w2 * fb.x; acc[2][3] += w2 * fb.y;
                acc[3][0] += w3 * fa.x; acc[3][1] += w3 * fa.y; acc[3][2] += w3 * fb.x; acc[3][3] += w3 * fb.y;
            }
        }
    }
    const size_t rb = (size_t)n * 1024;
#pragma unroll
    for (int h = 0; h < 4; h++) {
        float inv = 1.f / den[h];
        float z0 = acc[h][0] * inv, z1 = acc[h][1] * inv;
        float z2 = acc[h][2] * inv, z3 = acc[h][3] * inv;
        bf16 h0, l0, h1, l1, h2, l2, h3, l3;
        split_bf16(z0, h0, l0); split_bf16(z1, h1, l1);
        split_bf16(z2, h2, l2); split_bf16(z3, h3, l3);
        __nv_bfloat162 hpA, hpB, lpA, lpB;
        hpA.x = h0; hpA.y = h1; hpB.x = h2; hpB.y = h3;
        lpA.x = l0; lpA.y = l1; lpB.x = l2; lpB.y = l3;
        *(__nv_bfloat162*)&g_Zp[rb + h * 256 + lane * 4]           = hpA;
        *(__nv_bfloat162*)&g_Zp[rb + h * 256 + lane * 4 + 2]       = hpB;
        *(__nv_bfloat162*)&g_Zp[rb + h * 256 + 128 + lane * 4]     = lpA;
        *(__nv_bfloat162*)&g_Zp[rb + h * 256 + 128 + lane * 4 + 2] = lpB;
    }
}

// ================= 128-wide mma GEMM body, 4-stage pipeline =================
template <int ACT, int ATT>
__device__ __forceinline__ void mgemm_body(
    const bf16* __restrict__ Ap, const bf16* __restrict__ Bp,
    int K, int apitch, int bpitch, int Nn, int Wtot,
    const float* __restrict__ bias,
    float* __restrict__ Cf, __half* __restrict__ Ch, bf16* __restrict__ Cb2,
    const float* __restrict__ a_s, const float* __restrict__ a_d,
    float* __restrict__ atts, float* __restrict__ attd,
    int heads, int head, int row0, int col0, char* dyn)
{
    __shared__ float s_as[128], s_ad[128];
    const uint32_t dynu = smem_u32(dyn);

    const int tid = threadIdx.x;
    const int wid = tid >> 5, lane = tid & 31;
    const int g = lane >> 2, tig = lane & 3;
    const int warp_m = wid & 3, warp_n = wid >> 2;

    const int lrow = tid >> 1, lsel = tid & 1;
    const bf16* Agb = Ap + (size_t)(row0 + lrow) * apitch + lsel * K;
    const bf16* Bgb = Bp + (size_t)(col0 + lrow) * bpitch + lsel * K;
    const uint32_t soff = (uint32_t)lrow * 80u + (uint32_t)lsel * 32u;

    const int arow_l = (((lane >> 3) & 1) << 3) + (lane & 7);
    const int acol_l = (lane >> 4) << 3;
    const int brow_l = (lane & 7) + ((lane >> 4) << 3);
    const int bcol_l = ((lane >> 3) & 1) << 3;

    float c[2][8][4];
#pragma unroll
    for (int i = 0; i < 2; i++)
#pragma unroll
        for (int j = 0; j < 8; j++)
#pragma unroll
            for (int q = 0; q < 4; q++) c[i][j][q] = 0.f;

    const int NT = K >> 4;
#pragma unroll
    for (int p = 0; p < 3; p++) {
        if (p < NT) {
            const uint32_t st = dynu + (uint32_t)p * 20480u;
            const int koff = p * 16;
            cp_async16(st + soff, Agb + koff);
            cp_async16(st + soff + 16, Agb + koff + 8);
            cp_async16(st + 10240u + soff, Bgb + koff);
            cp_async16(st + 10240u + soff + 16, Bgb + koff + 8);
        }
        asm volatile("cp.async.commit_group;" ::: "memory");
    }

    for (int kt = 0; kt < NT; kt++) {
        const int rem = NT - 1 - kt;
        if (rem >= 2)      asm volatile("cp.async.wait_group 2;" ::: "memory");
        else if (rem == 1) asm volatile("cp.async.wait_group 1;" ::: "memory");
        else               asm volatile("cp.async.wait_group 0;" ::: "memory");
        __syncthreads();
        if (kt + 3 < NT) {
            const uint32_t st = dynu + (uint32_t)((kt + 3) & 3) * 20480u;
            const int koff = (kt + 3) * 16;
            cp_async16(st + soff, Agb + koff);
            cp_async16(st + soff + 16, Agb + koff + 8);
            cp_async16(st + 10240u + soff, Bgb + koff);
            cp_async16(st + 10240u + soff + 16, Bgb + koff + 8);
            asm volatile("cp.async.commit_group;" ::: "memory");
        }

        const uint32_t aBase = dynu + (uint32_t)(kt & 3) * 20480u;
        const uint32_t bBase = aBase + 10240u;

        uint32_t ah[2][4], al[2][4], bb[8][2];
#pragma unroll
        for (int mi = 0; mi < 2; mi++) {
            uint32_t r = aBase + (uint32_t)(warp_m * 32 + mi * 16 + arow_l) * 80u
                               + (uint32_t)acol_l * 2u;
            ldm_x4(ah[mi], r);
            ldm_x4(al[mi], r + 32u);
        }
#pragma unroll
        for (int p = 0; p < 4; p++) {
            uint32_t t[4];
            uint32_t r = bBase + (uint32_t)(warp_n * 64 + p * 16 + brow_l) * 80u
                               + (uint32_t)bcol_l * 2u;
            ldm_x4(t, r);
            bb[2 * p][0] = t[0]; bb[2 * p][1] = t[1];
            bb[2 * p + 1][0] = t[2]; bb[2 * p + 1][1] = t[3];
        }
#pragma unroll
        for (int mi = 0; mi < 2; mi++)
#pragma unroll
            for (int ni = 0; ni < 8; ni++)
                mma_bf16(c[mi][ni], ah[mi], bb[ni]);
#pragma unroll
        for (int mi = 0; mi < 2; mi++)
#pragma unroll
            for (int ni = 0; ni < 8; ni++)
                mma_bf16(c[mi][ni], al[mi], bb[ni]);
#pragma unroll
        for (int p = 0; p < 4; p++) {
            uint32_t t[4];
            uint32_t r = bBase + (uint32_t)(warp_n * 64 + p * 16 + brow_l) * 80u
                               + (uint32_t)bcol_l * 2u + 32u;
            ldm_x4(t, r);
            bb[2 * p][0] = t[0]; bb[2 * p][1] = t[1];
            bb[2 * p + 1][0] = t[2]; bb[2 * p + 1][1] = t[3];
        }
#pragma unroll
        for (int mi = 0; mi < 2; mi++)
#pragma unroll
            for (int ni = 0; ni < 8; ni++)
                mma_bf16(c[mi][ni], ah[mi], bb[ni]);
    }

    if (ATT) {
        __syncthreads();
        if (tid < 128) { s_as[tid] = 0.f; s_ad[tid] = 0.f; }
        __syncthreads();
    }

    float ssv[2][2] = {{0.f, 0.f}, {0.f, 0.f}};
    float sdv[2][2] = {{0.f, 0.f}, {0.f, 0.f}};

#pragma unroll
    for (int ni = 0; ni < 8; ni++) {
        const int cA = col0 + warp_n * 64 + ni * 8 + tig * 2;
        float b0 = 0.f, b1 = 0.f;
        if (bias) { b0 = __ldg(&bias[cA]); b1 = __ldg(&bias[cA + 1]); }
        float asA = 0.f, asB = 0.f, adA = 0.f, adB = 0.f;
        if (ATT) {
            asA = __ldg(&a_s[cA]); asB = __ldg(&a_s[cA + 1]);
            adA = __ldg(&a_d[cA]); adB = __ldg(&a_d[cA + 1]);
        }
#pragma unroll
        for (int mi = 0; mi < 2; mi++) {
            const int r0g = row0 + warp_m * 32 + mi * 16 + g;
            const int r1g = r0g + 8;
            float v00 = c[mi][ni][0] + b0, v01 = c[mi][ni][1] + b1;
            float v10 = c[mi][ni][2] + b0, v11 = c[mi][ni][3] + b1;
            if (ACT == 2) {
                v00 = eluf(v00); v01 = eluf(v01);
                v10 = eluf(v10); v11 = eluf(v11);
            }
            if (ATT) {
                ssv[mi][0] += v00 * asA + v01 * asB;
                ssv[mi][1] += v10 * asA + v11 * asB;
                sdv[mi][0] += v00 * adA + v01 * adB;
                sdv[mi][1] += v10 * adA + v11 * adB;
            }
            if (Cf) {
                *(float2*)&Cf[(size_t)r0g * Nn + cA] = make_float2(v00, v01);
                *(float2*)&Cf[(size_t)r1g * Nn + cA] = make_float2(v10, v11);
            }
            if (Ch) {
                *(__half2*)&Ch[(size_t)r0g * Nn + cA] = __floats2half2_rn(v00, v01);
                *(__half2*)&Ch[(size_t)r1g * Nn + cA] = __floats2half2_rn(v10, v11);
            }
            if (Cb2) {
                bf16 h0, l0, h1, l1;
                __nv_bfloat162 hp, lp;
                size_t rb0 = (size_t)r0g * 2 * Wtot;
                split_bf16(v00, h0, l0); split_bf16(v01, h1, l1);
                hp.x = h0; hp.y = h1; lp.x = l0; lp.y = l1;
                *(__nv_bfloat162*)&Cb2[rb0 + cA]        = hp;
                *(__nv_bfloat162*)&Cb2[rb0 + Wtot + cA] = lp;
                size_t rb1 = (size_t)r1g * 2 * Wtot;
                split_bf16(v10, h0, l0); split_bf16(v11, h1, l1);
                hp.x = h0; hp.y = h1; lp.x = l0; lp.y = l1;
                *(__nv_bfloat162*)&Cb2[rb1 + cA]        = hp;
                *(__nv_bfloat162*)&Cb2[rb1 + Wtot + cA] = lp;
            }
        }
    }

    if (ATT) {
#pragma unroll
        for (int mi = 0; mi < 2; mi++) {
            const int rl0 = warp_m * 32 + mi * 16 + g;
            atomicAdd(&s_as[rl0], ssv[mi][0]);
            atomicAdd(&s_as[rl0 + 8], ssv[mi][1]);
            atomicAdd(&s_ad[rl0], sdv[mi][0]);
            atomicAdd(&s_ad[rl0 + 8], sdv[mi][1]);
        }
        __syncthreads();
        if (tid < 128) {
            const int row = row0 + tid;
            atts[row * heads + head] = s_as[tid];
            attd[row * heads + head] = s_ad[tid];
        }
    }
}

__global__ void __launch_bounds__(256) k_gemmZ(const float* __restrict__ b1) {
    extern __shared__ char dyn[];
    const int head = blockIdx.x;
    mgemm_body<2, 0>(g_Zp + head * 256, g_W1t, 128, 1024, 256, 512, 512,
                     b1, nullptr, nullptr, g_e1p,
                     nullptr, nullptr, nullptr, nullptr,
                     1, 0, blockIdx.y * 128, head * 128, dyn);
}
__global__ void __launch_bounds__(256) k_mgemm2(const float* __restrict__ as2,
                                                const float* __restrict__ ad2) {
    extern __shared__ char dyn[];
    mgemm_body<0, 1>(g_e1p, g_W2t, 512, 1024, 1024, 128, 0,
                     nullptr, nullptr, g_h2h, nullptr,
                     as2, ad2, g_att2s, g_att2d,
                     1, 0, blockIdx.x * 128, 0, dyn);
}

// ================= fused node MLP (now with agg2 stage 0) =================
// All GEMM stages read A from smem chunks (AFROM=1 only).
__device__ __forceinline__ void gemm_stage_c(
    float (&c)[2][8][4],
    const bf16* Bgb,
    uint32_t aChunkBase, uint32_t sBs, uint32_t soff,
    int warp_m, int warp_n, int arow_l, int acol_l, int brow_l, int bcol_l)
{
#pragma unroll
    for (int i = 0; i < 2; i++)
#pragma unroll
        for (int j = 0; j < 8; j++)
#pragma unroll
            for (int q = 0; q < 4; q++) c[i][j][q] = 0.f;

    cp_async16(sBs + soff, Bgb);
    cp_async16(sBs + soff + 16, Bgb + 8);
    asm volatile("cp.async.commit_group;" ::: "memory");

#pragma unroll
    for (int kt = 0; kt < 8; kt++) {
        const int buf = kt & 1;
        if (kt + 1 < 8) {
            const int koff = (kt + 1) * 16;
            const uint32_t bofs = ((kt + 1) & 1) ? 10240u : 0u;
            cp_async16(sBs + bofs + soff, Bgb + koff);
            cp_async16(sBs + bofs + soff + 16, Bgb + koff + 8);
            asm volatile("cp.async.commit_group;" ::: "memory");
            asm volatile("cp.async.wait_group 1;" ::: "memory");
        } else {
            asm volatile("cp.async.wait_group 0;" ::: "memory");
        }
        __syncthreads();
        const uint32_t aBase = aChunkBase + (uint32_t)kt * 10240u;
        const uint32_t bBase = sBs + (uint32_t)buf * 10240u;

        uint32_t ah[2][4], al[2][4], bb[8][2];
#pragma unroll
        for (int mi = 0; mi < 2; mi++) {
            uint32_t r = aBase + (uint32_t)(warp_m * 32 + mi * 16 + arow_l) * 80u
                               + (uint32_t)acol_l * 2u;
            ldm_x4(ah[mi], r);
            ldm_x4(al[mi], r + 32u);
        }
#pragma unroll
        for (int p = 0; p < 4; p++) {
            uint32_t t[4];
            uint32_t r = bBase + (uint32_t)(warp_n * 64 + p * 16 + brow_l) * 80u
                               + (uint32_t)bcol_l * 2u;
            ldm_x4(t, r);
            bb[2 * p][0] = t[0]; bb[2 * p][1] = t[1];
            bb[2 * p + 1][0] = t[2]; bb[2 * p + 1][1] = t[3];
        }
#pragma unroll
        for (int mi = 0; mi < 2; mi++)
#pragma unroll
            for (int ni = 0; ni < 8; ni++)
                mma_bf16(c[mi][ni], ah[mi], bb[ni]);
#pragma unroll
        for (int mi = 0; mi < 2; mi++)
#pragma unroll
            for (int ni = 0; ni < 8; ni++)
                mma_bf16(c[mi][ni], al[mi], bb[ni]);
#pragma unroll
        for (int p = 0; p < 4; p++) {
            uint32_t t[4];
            uint32_t r = bBase + (uint32_t)(warp_n * 64 + p * 16 + brow_l) * 80u
                               + (uint32_t)bcol_l * 2u + 32u;
            ldm_x4(t, r);
            bb[2 * p][0] = t[0]; bb[2 * p][1] = t[1];
            bb[2 * p + 1][0] = t[2]; bb[2 * p + 1][1] = t[3];
        }
#pragma unroll
        for (int mi = 0; mi < 2; mi++)
#pragma unroll
            for (int ni = 0; ni < 8; ni++)
                mma_bf16(c[mi][ni], ah[mi], bb[ni]);
        __syncthreads();
    }
}

__device__ __forceinline__ void store_split(char* base, int row, int col, float v0, float v1) {
    bf16 h0, l0, h1, l1;
    split_bf16(v0, h0, l0);
    split_bf16(v1, h1, l1);
    char* p = base + (col >> 4) * 10240 + row * 80 + (col & 15) * 2;
    __nv_bfloat162 hp, lp;
    hp.x = h0; hp.y = h1; lp.x = l0; lp.y = l1;
    *(__nv_bfloat162*)p = hp;
    *(__nv_bfloat162*)(p + 32) = lp;
}

// dyn layout: [0, 81920) chunk area A; [81920, 163840) chunk area B;
//             [163840, 184320) B-tile double buffer (2 x 10240)
__global__ void __launch_bounds__(256) k_nodeMLP(const float* __restrict__ b2,
                                                 const float* __restrict__ bo1,
                                                 const float* __restrict__ bo2,
                                                 float* __restrict__ xo,
                                                 __half* __restrict__ PQh) {
    extern __shared__ char dyn[];
    char* areaA = dyn;
    char* areaB = dyn + 81920;
    const uint32_t dynu = smem_u32(dyn);
    const uint32_t areaAU = dynu;
    const uint32_t areaBU = dynu + 81920u;
    const uint32_t sBs    = dynu + 163840u;

    const int tid = threadIdx.x;
    const int wid = tid >> 5, lane = tid & 31;
    const int g = lane >> 2, tig = lane & 3;
    const int warp_m = wid & 3, warp_n = wid >> 2;
    const int row0 = blockIdx.x * 128;
    const int lrow = tid >> 1, lsel = tid & 1;
    const uint32_t soff = (uint32_t)lrow * 80u + (uint32_t)lsel * 32u;
    const int arow_l = (((lane >> 3) & 1) << 3) + (lane & 7);
    const int acol_l = (lane >> 4) << 3;
    const int brow_l = (lane & 7) + ((lane >> 4) << 3);
    const int bcol_l = ((lane >> 3) & 1) << 3;

    // ---- stage 0: agg2 for my 128 rows -> t split into areaA
    {
        const float4 bv = *(const float4*)&b2[lane * 4];
#pragma unroll 1
        for (int i = 0; i < 16; i++) {
            const int nl = wid * 16 + i;
            const int n = row0 + nl;
            const int beg = g_off[n], end = g_off[n + 1];
            const float adn = g_att2d[n];
            float acc[4] = {0.f, 0.f, 0.f, 0.f};
            float den = 0.f;
            for (int c0 = beg; c0 < end; c0 += 32) {
                const int m = min(32, end - c0);
                int   sj = 0;
                float ej = 0.f;
                if (lane < m) {
                    sj = g_csrc[c0 + lane];
                    ej = expf(lrelu02(g_att2s[sj] + adn));
                }
                const int mr = (m + 7) & ~7;
                for (int j0 = 0; j0 < mr; j0 += 8) {
#pragma unroll
                    for (int jj = 0; jj < 8; jj++) {
                        const int j = j0 + jj;
                        int   s = __shfl_sync(0xffffffffu, sj, j);
                        float w = __shfl_sync(0xffffffffu, ej, j);
                        uint2 hv = *(const uint2*)&g_h2h[(size_t)s * 128 + lane * 4];
                        float2 fa = __half22float2(*(const __half2*)&hv.x);
                        float2 fb = __half22float2(*(const __half2*)&hv.y);
                        den += w;
                        acc[0] += w * fa.x; acc[1] += w * fa.y;
                        acc[2] += w * fb.x; acc[3] += w * fb.y;
                    }
                }
            }
            const float inv = 1.f / den;
            float o0 = eluf(acc[0] * inv + bv.x), o1 = eluf(acc[1] * inv + bv.y);
            float o2 = eluf(acc[2] * inv + bv.z), o3 = eluf(acc[3] * inv + bv.w);
            store_split(areaA, nl, lane * 4, o0, o1);
            store_split(areaA, nl, lane * 4 + 2, o2, o3);
        }
    }
    // ordering to stage 1's A reads is provided by gemm_stage_c's kt=0 barrier

    float c[2][8][4];

    // ---- stage 1: u = relu(t @ Wo1 + bo1) -> areaB
    {
        const bf16* Bgb = g_Wo1t + (size_t)lrow * 256 + lsel * 128;
        gemm_stage_c(c, Bgb, areaAU, sBs, soff,
                     warp_m, warp_n, arow_l, acol_l, brow_l, bcol_l);
#pragma unroll
        for (int ni = 0; ni < 8; ni++) {
            const int col = warp_n * 64 + ni * 8 + tig * 2;
            const float b0 = __ldg(&bo1[col]), b1 = __ldg(&bo1[col + 1]);
#pragma unroll
            for (int mi = 0; mi < 2; mi++) {
                const int r0l = warp_m * 32 + mi * 16 + g;
                store_split(areaB, r0l, col,
                            fmaxf(c[mi][ni][0] + b0, 0.f), fmaxf(c[mi][ni][1] + b1, 0.f));
                store_split(areaB, r0l + 8, col,
                            fmaxf(c[mi][ni][2] + b0, 0.f), fmaxf(c[mi][ni][3] + b1, 0.f));
            }
        }
        __syncthreads();
    }

    // ---- stage 2: xo = u @ Wo2 + bo2 -> global + areaA (overwrite t)
    {
        const bf16* Bgb = g_Wo2t + (size_t)lrow * 256 + lsel * 128;
        gemm_stage_c(c, Bgb, areaBU, sBs, soff,
                     warp_m, warp_n, arow_l, acol_l, brow_l, bcol_l);
#pragma unroll
        for (int ni = 0; ni < 8; ni++) {
            const int col = warp_n * 64 + ni * 8 + tig * 2;
            const float b0 = __ldg(&bo2[col]), b1 = __ldg(&bo2[col + 1]);
#pragma unroll
            for (int mi = 0; mi < 2; mi++) {
                const int r0l = warp_m * 32 + mi * 16 + g;
                const int r1l = r0l + 8;
                float v00 = c[mi][ni][0] + b0, v01 = c[mi][ni][1] + b1;
                float v10 = c[mi][ni][2] + b0, v11 = c[mi][ni][3] + b1;
                *(float2*)&xo[(size_t)(row0 + r0l) * 128 + col] = make_float2(v00, v01);
                *(float2*)&xo[(size_t)(row0 + r1l) * 128 + col] = make_float2(v10, v11);
                store_split(areaA, r0l, col, v00, v01);
                store_split(areaA, r1l, col, v10, v11);
            }
        }
        __syncthreads();
    }

    // ---- stage 3: PQ = xo @ WePQ + bePQ -> global fp16, two 128-col passes
#pragma unroll
    for (int p = 0; p < 2; p++) {
        const bf16* Bgb = g_WePQt + (size_t)(p * 128 + lrow) * 256 + lsel * 128;
        gemm_stage_c(c, Bgb, areaAU, sBs, soff,
                     warp_m, warp_n, arow_l, acol_l, brow_l, bcol_l);
#pragma unroll
        for (int ni = 0; ni < 8; ni++) {
            const int col = warp_n * 64 + ni * 8 + tig * 2;
            const int gcol = p * 128 + col;
            const float b0 = g_bePQ[gcol], b1 = g_bePQ[gcol + 1];
#pragma unroll
            for (int mi = 0; mi < 2; mi++) {
                const int r0g = row0 + warp_m * 32 + mi * 16 + g;
                const int r1g = r0g + 8;
                *(__half2*)&PQh[(size_t)r0g * 256 + gcol] =
                    __floats2half2_rn(c[mi][ni][0] + b0, c[mi][ni][1] + b1);
                *(__half2*)&PQh[(size_t)r1g * 256 + gcol] =
                    __floats2half2_rn(c[mi][ni][2] + b0, c[mi][ni][3] + b1);
            }
        }
    }
}

// ================= edge MLP v3: 128 edges/block =================
__global__ void __launch_bounds__(256) k_edge_final(const void* __restrict__ ei,
                                                    const float* __restrict__ eattr,
                                                    const float* __restrict__ We1,
                                                    const float* __restrict__ We2,
                                                    const float* __restrict__ be2,
                                                    float* __restrict__ out) {
    __shared__ float  sW1f[16 * 128];
    __shared__ __half sHid[128][136];
    __shared__ __half sW2h[16][136];
    const int tid = threadIdx.x, wid = tid >> 5, lane = tid & 31;

    for (int i = tid; i < 2048; i += 256) {
        sW1f[i] = We1[256 * 128 + i];
        int cc = i >> 4, o = i & 15;
        sW2h[o][cc] = __float2half(We2[i]);
    }
    __syncthreads();

    float4 w1r[16];
#pragma unroll
    for (int k = 0; k < 16; k++) w1r[k] = *(const float4*)&sW1f[k * 128 + lane * 4];

    const int is64 = g_is64;
    const long e0 = (long)blockIdx.x * 128;

#pragma unroll
    for (int r = 0; r < 16; r++) {
        const long e = e0 + wid * 16 + r;
        int s = idx_at(ei, e, is64);
        int d = idx_at(ei, (long)EE + e, is64);
        uint2 pv = *(const uint2*)&g_PQh[(size_t)s * 256 + lane * 4];
        uint2 qv = *(const uint2*)&g_PQh[(size_t)d * 256 + 128 + lane * 4];
        float2 pa = __half22float2(*(const __half2*)&pv.x);
        float2 pb = __half22float2(*(const __half2*)&pv.y);
        float2 qa = __half22float2(*(const __half2*)&qv.x);
        float2 qb = __half22float2(*(const __half2*)&qv.y);
        float4 hv;
        hv.x = pa.x + qa.x; hv.y = pa.y + qa.y;
        hv.z = pb.x + qb.x; hv.w = pb.y + qb.y;
        float eav = (lane < 16) ? eattr[e * 16 + lane] : 0.f;
#pragma unroll
        for (int k = 0; k < 16; k++) {
            float ek = __shfl_sync(0xffffffffu, eav, k);
            hv.x += ek * w1r[k].x; hv.y += ek * w1r[k].y;
            hv.z += ek * w1r[k].z; hv.w += ek * w1r[k].w;
        }
        __half2 h01 = __floats2half2_rn(fmaxf(hv.x, 0.f), fmaxf(hv.y, 0.f));
        __half2 h23 = __floats2half2_rn(fmaxf(hv.z, 0.f), fmaxf(hv.w, 0.f));
        uint2 packed;
        packed.x = *(uint32_t*)&h01;
        packed.y = *(uint32_t*)&h23;
        *(uint2*)&sHid[wid * 16 + r][lane * 4] = packed;
    }
    __syncthreads();

    {
        const int g = lane >> 2, tig = lane & 3;
        const int arow_l = (((lane >> 3) & 1) << 3) + (lane & 7);
        const int acol_l = (lane >> 4) << 3;
        const int brow_l = (lane & 7) + ((lane >> 4) << 3);
        const int bcol_l = ((lane >> 3) & 1) << 3;
        const uint32_t sA = smem_u32(&sHid[wid * 16][0]);
        const uint32_t sB = smem_u32(&sW2h[0][0]);

        float c0[4] = {0.f, 0.f, 0.f, 0.f};
        float c1[4] = {0.f, 0.f, 0.f, 0.f};
#pragma unroll
        for (int kk = 0; kk < 128; kk += 16) {
            uint32_t af[4], bfr[4];
            ldm_x4(af, sA + (uint32_t)arow_l * 272u + (uint32_t)(kk + acol_l) * 2u);
            ldm_x4(bfr, sB + (uint32_t)brow_l * 272u + (uint32_t)(kk + bcol_l) * 2u);
            mma_f16(c0, af, bfr);
            mma_f16(c1, af, bfr + 2);
        }

        const long eA = e0 + wid * 16 + g;
        const long eB = eA + 8;
        const float b0 = __ldg(&be2[tig * 2]),     b1 = __ldg(&be2[tig * 2 + 1]);
        const float b8 = __ldg(&be2[8 + tig * 2]), b9 = __ldg(&be2[8 + tig * 2 + 1]);
        *(float2*)&out[eA * 16 + tig * 2]     = make_float2(c0[0] + b0, c0[1] + b1);
        *(float2*)&out[eB * 16 + tig * 2]     = make_float2(c0[2] + b0, c0[3] + b1);
        *(float2*)&out[eA * 16 + 8 + tig * 2] = make_float2(c1[0] + b8, c1[1] + b9);
        *(float2*)&out[eB * 16 + 8 + tig * 2] = make_float2(c1[2] + b8, c1[3] + b9);
    }
}

// ================= launcher =================
extern "C" void kernel_launch(void* const* d_in, const int* in_sizes, int n_in,
                              void* d_out, int out_size) {
    const float* x    = (const float*)d_in[0];
    const void*  ei   = d_in[1];
    const float* eatt = (const float*)d_in[2];
    const float* W1   = (const float*)d_in[3];
    const float* as1  = (const float*)d_in[4];
    const float* ad1  = (const float*)d_in[5];
    const float* b1   = (const float*)d_in[6];
    const float* W2   = (const float*)d_in[7];
    const float* as2  = (const float*)d_in[8];
    const float* ad2  = (const float*)d_in[9];
    const float* b2   = (const float*)d_in[10];
    const float* Wo1  = (const float*)d_in[11];
    const float* bo1  = (const float*)d_in[12];
    const float* Wo2  = (const float*)d_in[13];
    const float* bo2  = (const float*)d_in[14];
    const float* We1  = (const float*)d_in[15];
    const float* be1  = (const float*)d_in[16];
    const float* We2  = (const float*)d_in[17];
    const float* be2  = (const float*)d_in[18];

    float* out  = (float*)d_out;
    float* xo   = out;
    float* eout = out + (size_t)NN * 128;

    __half* PQh;
    cudaGetSymbolAddress((void**)&PQh, g_PQh);

    cudaFuncSetAttribute(k_gemmZ, cudaFuncAttributeMaxDynamicSharedMemorySize, 81920);
    cudaFuncSetAttribute(k_mgemm2, cudaFuncAttributeMaxDynamicSharedMemorySize, 81920);
    cudaFuncSetAttribute(k_nodeMLP, cudaFuncAttributeMaxDynamicSharedMemorySize, 184320);

    // 0: prep = xh | convW | init | va
    k_prep<<<16899, 256>>>(x, (const int*)ei, W1, W2, Wo1, Wo2, We1, be1, as1, ad1);
    // 1: hist | attdot (fused)
    k_histdot<<<2125 + 4000, 256>>>(ei);
    // 2: scan
    k_scan_all<<<1, 1024>>>();
    // 3: scatter (profiled slot)
    k_scatter<<<2125, 256>>>(ei);
    // 4: agg1x
    k_agg1x<<<4000, 256>>>();
    // 5: gemmZ
    k_gemmZ<<<dim3(4, 250), 256, 81920>>>(b1);
    // 6: gemm2
    k_mgemm2<<<250, 256, 81920>>>(as2, ad2);
    // 7: node MLP (agg2 fused as stage 0)
    k_nodeMLP<<<250, 256, 184320>>>(b2, bo1, bo2, xo, PQh);
    // 8: edge MLP v3
    k_edge_final<<<EE / 128, 256>>>(ei, eatt, We1, We2, be2, eout);
}

// round 15
// speedup vs baseline: 1.0928x; 1.0928x over previous
#include <cuda_runtime.h>
#include <cuda_bf16.h>
#include <cuda_fp16.h>
#include <cstdint>

#define NN 32000
#define EE 512000
#define ET (EE + NN)
#define DD 128
#define HH 4
#define EAD 16

typedef __nv_bfloat16 bf16;

// ================= scratch =================
__device__ int   g_is64;
__device__ int   g_deg[NN];
__device__ int   g_off[NN + 1];
__device__ int   g_cur[NN];
__device__ int   g_csrc[ET];

__device__ __half g_xh [(size_t)NN * 128];
__device__ __half g_h2h[(size_t)NN * 128];
__device__ __half g_PQh[(size_t)NN * 256];
__device__ float g_att1s[NN * 4];
__device__ float g_att1d[NN * 4];
__device__ float g_att2s[NN];
__device__ float g_att2d[NN];
__device__ float g_bePQ[256];
__device__ float g_va[8 * 128];

__device__ bf16  g_Zp [(size_t)NN * 1024];
__device__ bf16  g_e1p[(size_t)NN * 1024];
__device__ bf16  g_tp [(size_t)NN * 256];
__device__ bf16  g_W1t  [512 * 256];
__device__ bf16  g_W2t  [128 * 1024];
__device__ bf16  g_Wo1t [128 * 256];
__device__ bf16  g_Wo2t [128 * 256];
__device__ bf16  g_WePQt[256 * 256];

// ================= helpers =================
__device__ __forceinline__ float lrelu02(float a) { return a > 0.f ? a : 0.2f * a; }
__device__ __forceinline__ float eluf(float v)    { return v > 0.f ? v : expm1f(v); }
__device__ __forceinline__ int idx_at(const void* ei, long pos, int is64) {
    if (is64) return (int)((const long long*)ei)[pos];
    return ((const int*)ei)[pos];
}
__device__ __forceinline__ void split_bf16(float v, bf16& h, bf16& l) {
    h = __float2bfloat16(v);
    l = __float2bfloat16(v - __bfloat162float(h));
}
__device__ __forceinline__ uint32_t smem_u32(const void* p) {
    uint32_t a;
    asm("{ .reg .u64 t; cvta.to.shared.u64 t, %1; cvt.u32.u64 %0, t; }" : "=r"(a) : "l"(p));
    return a;
}
__device__ __forceinline__ void cp_async16(uint32_t saddr, const void* g) {
    asm volatile("cp.async.cg.shared.global [%0], [%1], 16;" :: "r"(saddr), "l"(g));
}
__device__ __forceinline__ void mma_bf16(float* c, const uint32_t* a, const uint32_t* b) {
    asm volatile(
        "mma.sync.aligned.m16n8k16.row.col.f32.bf16.bf16.f32 "
        "{%0,%1,%2,%3}, {%4,%5,%6,%7}, {%8,%9}, {%0,%1,%2,%3};"
        : "+f"(c[0]), "+f"(c[1]), "+f"(c[2]), "+f"(c[3])
        : "r"(a[0]), "r"(a[1]), "r"(a[2]), "r"(a[3]), "r"(b[0]), "r"(b[1]));
}
__device__ __forceinline__ void mma_f16(float* c, const uint32_t* a, const uint32_t* b) {
    asm volatile(
        "mma.sync.aligned.m16n8k16.row.col.f32.f16.f16.f32 "
        "{%0,%1,%2,%3}, {%4,%5,%6,%7}, {%8,%9}, {%0,%1,%2,%3};"
        : "+f"(c[0]), "+f"(c[1]), "+f"(c[2]), "+f"(c[3])
        : "r"(a[0]), "r"(a[1]), "r"(a[2]), "r"(a[3]), "r"(b[0]), "r"(b[1]));
}
__device__ __forceinline__ void ldm_x4(uint32_t* r, uint32_t addr) {
    asm volatile("ldmatrix.sync.aligned.m8n8.x4.shared.b16 {%0,%1,%2,%3}, [%4];"
                 : "=r"(r[0]), "=r"(r[1]), "=r"(r[2]), "=r"(r[3]) : "r"(addr));
}

// ================= prep: xh (vectorized) | convW | init | va =================
__device__ __forceinline__ void conv_emit(const float* W, bf16* Wt, int K, int N, int idx) {
    int n = idx / K;
    int k = idx - n * K;
    bf16 h, l;
    split_bf16(W[(size_t)k * N + n], h, l);
    bf16* row = Wt + (size_t)n * 2 * K;
    row[k] = h; row[K + k] = l;
}
__global__ void __launch_bounds__(256) k_prep(const float* x, const int* eiw,
                                              const float* W1, const float* W2,
                                              const float* Wo1, const float* Wo2,
                                              const float* We1, const float* be1,
                                              const float* as1, const float* ad1) {
    const int b = blockIdx.x, tid = threadIdx.x;
    if (b < 4000) {
        // xh: float4 -> 2x half2 (4 elems/thread); 4000*256*4 = 4,096,000
        long i4 = ((long)b * 256 + tid) * 4;
        float4 v = *(const float4*)&x[i4];
        *(__half2*)&g_xh[i4]     = __floats2half2_rn(v.x, v.y);
        *(__half2*)&g_xh[i4 + 2] = __floats2half2_rn(v.z, v.w);
    } else if (b < 4770) {
        int i = (b - 4000) * 256 + tid;
        if (i < 65536)          conv_emit(W1,  g_W1t,  128, 512, i);
        else if (i < 131072)    conv_emit(W2,  g_W2t,  512, 128, i - 65536);
        else if (i < 147456)    conv_emit(Wo1, g_Wo1t, 128, 128, i - 131072);
        else if (i < 163840)    conv_emit(Wo2, g_Wo2t, 128, 128, i - 147456);
        else if (i < 180224)    conv_emit(We1, g_WePQt, 128, 128, i - 163840);
        else if (i < 196608)    conv_emit(We1 + 128 * 128, g_WePQt + 128 * 256, 128, 128, i - 180224);
        else if (i < 196864) {
            int j = i - 196608;
            g_bePQ[j] = (j < 128) ? be1[j] : 0.f;
        }
    } else if (b < 4895) {
        int i = (b - 4770) * 256 + tid;
        g_deg[i] = 0;
        if (b == 4770) {
            __shared__ int s_any;
            if (tid == 0) s_any = 0;
            __syncthreads();
            int any = 0;
            for (int j = tid; j < 1024; j += 256) any |= eiw[2 * j + 1];
            if (any) atomicOr(&s_any, 1);
            __syncthreads();
            if (tid == 0) g_is64 = (s_any == 0) ? 1 : 0;
        }
    } else {
        int v = (b - 4895) * 2 + (tid >> 7);
        int k = tid & 127;
        const float* a = (v < 4) ? (as1 + v * 128) : (ad1 + (v - 4) * 128);
        int hh = (v < 4) ? v : (v - 4);
        const float* wrow = W1 + (size_t)k * 512 + hh * 128;
        float s = 0.f;
#pragma unroll 4
        for (int c = 0; c < 128; c++) s += wrow[c] * a[c];
        g_va[v * 128 + k] = s;
    }
}

// ================= fused hist | attdot =================
__global__ void __launch_bounds__(256) k_histdot(const void* ei) {
    const int b = blockIdx.x, tid = threadIdx.x;
    if (b < 2125) {
        int is64 = g_is64;
        long e = (long)b * 256 + tid;
        int d = (e < EE) ? idx_at(ei, (long)EE + e, is64) : (int)(e - EE);
        atomicAdd(&g_deg[d], 1);
    } else {
        __shared__ float sva[1024];
        for (int i = tid; i < 1024; i += 256) sva[i] = g_va[i];
        __syncthreads();
        const int w = tid >> 5, lane = tid & 31;
        const int n = (b - 2125) * 8 + w;
        uint2 xv2 = *(const uint2*)&g_xh[(size_t)n * 128 + lane * 4];
        float2 xa = __half22float2(*(const __half2*)&xv2.x);
        float2 xb = __half22float2(*(const __half2*)&xv2.y);
        float dots[8];
#pragma unroll
        for (int v = 0; v < 8; v++) {
            float4 vv = *(const float4*)&sva[v * 128 + lane * 4];
            dots[v] = xa.x * vv.x + xa.y * vv.y + xb.x * vv.z + xb.y * vv.w;
        }
#pragma unroll
        for (int off = 16; off; off >>= 1)
#pragma unroll
            for (int v = 0; v < 8; v++)
                dots[v] += __shfl_xor_sync(0xffffffffu, dots[v], off);
        if (lane < 4)      g_att1s[n * 4 + lane] = dots[lane];
        else if (lane < 8) g_att1d[n * 4 + lane - 4] = dots[lane];
    }
}

__global__ void __launch_bounds__(1024) k_scan_all() {
    __shared__ int wsum[32];
    const int t = threadIdx.x, lane = t & 31, w = t >> 5;
    const int base = t * 32;
    int loc[32];
    int s = 0;
    if (base < NN) {
#pragma unroll
        for (int i = 0; i < 8; i++) {
            int4 v = *(const int4*)&g_deg[base + i * 4];
            loc[i * 4 + 0] = v.x; loc[i * 4 + 1] = v.y;
            loc[i * 4 + 2] = v.z; loc[i * 4 + 3] = v.w;
            s += v.x + v.y + v.z + v.w;
        }
    }
    int inc = s;
#pragma unroll
    for (int off = 1; off < 32; off <<= 1) {
        int xx = __shfl_up_sync(0xffffffffu, inc, off);
        if (lane >= off) inc += xx;
    }
    if (lane == 31) wsum[w] = inc;
    __syncthreads();
    if (w == 0) {
        int v = wsum[lane];
        int vi = v;
#pragma unroll
        for (int off = 1; off < 32; off <<= 1) {
            int xx = __shfl_up_sync(0xffffffffu, vi, off);
            if (lane >= off) vi += xx;
        }
        wsum[lane] = vi;
    }
    __syncthreads();
    const int warpoff = (w == 0) ? 0 : wsum[w - 1];
    int run = warpoff + inc - s;
    if (base < NN) {
#pragma unroll
        for (int i = 0; i < 32; i++) {
            g_off[base + i] = run;
            g_cur[base + i] = run;
            run += loc[i];
        }
    }
    if (t == 0) g_off[NN] = wsum[31];
}
__global__ void k_scatter(const void* ei) {
    int is64 = g_is64;
    long e = (long)blockIdx.x * 256 + threadIdx.x;
    int s, d;
    if (e < EE) {
        s = idx_at(ei, e, is64);
        d = idx_at(ei, (long)EE + e, is64);
    } else {
        s = d = (int)(e - EE);
    }
    int pos = atomicAdd(&g_cur[d], 1);
    g_csrc[pos] = s;
}

// ================= agg1x: warp-per-node =================
__global__ void __launch_bounds__(256) k_agg1x() {
    const int tid = threadIdx.x, wid = tid >> 5, lane = tid & 31;
    const int n = blockIdx.x * 8 + wid;
    const int beg = g_off[n], end = g_off[n + 1];

    const float4 ad = *(const float4*)&g_att1d[n * 4];
    float acc[4][4];
#pragma unroll
    for (int h = 0; h < 4; h++)
#pragma unroll
        for (int q = 0; q < 4; q++) acc[h][q] = 0.f;
    float den[4] = {0.f, 0.f, 0.f, 0.f};

    for (int c0 = beg; c0 < end; c0 += 32) {
        const int m = min(32, end - c0);
        int   sj = 0;
        float4 e4 = make_float4(0.f, 0.f, 0.f, 0.f);
        if (lane < m) {
            sj = g_csrc[c0 + lane];
            float4 as = *(const float4*)&g_att1s[sj * 4];
            e4.x = expf(lrelu02(as.x + ad.x));
            e4.y = expf(lrelu02(as.y + ad.y));
            e4.z = expf(lrelu02(as.z + ad.z));
            e4.w = expf(lrelu02(as.w + ad.w));
        }
        const int mr = (m + 7) & ~7;
        for (int j0 = 0; j0 < mr; j0 += 8) {
#pragma unroll
            for (int jj = 0; jj < 8; jj++) {
                const int j = j0 + jj;
                int   s  = __shfl_sync(0xffffffffu, sj,  j);
                float w0 = __shfl_sync(0xffffffffu, e4.x, j);
                float w1 = __shfl_sync(0xffffffffu, e4.y, j);
                float w2 = __shfl_sync(0xffffffffu, e4.z, j);
                float w3 = __shfl_sync(0xffffffffu, e4.w, j);
                uint2 xv = *(const uint2*)&g_xh[(size_t)s * 128 + lane * 4];
                float2 fa = __half22float2(*(const __half2*)&xv.x);
                float2 fb = __half22float2(*(const __half2*)&xv.y);
                den[0] += w0; den[1] += w1; den[2] += w2; den[3] += w3;
                acc[0][0] += w0 * fa.x; acc[0][1] += w0 * fa.y; acc[0][2] += w0 * fb.x; acc[0][3] += w0 * fb.y;
                acc[1][0] += w1 * fa.x; acc[1][1] += w1 * fa.y; acc[1][2] += w1 * fb.x; acc[1][3] += w1 * fb.y;
                acc[2][0] += w2 * fa.x; acc[2][1] += w2 * fa.y; acc[2][2] += w2 * fb.x; acc[2][3] += w2 * fb.y;
                acc[3][0] += w3 * fa.x; acc[3][1] += w3 * fa.y; acc[3][2] += w3 * fb.x; acc[3][3] += w3 * fb.y;
            }
        }
    }
    const size_t rb = (size_t)n * 1024;
#pragma unroll
    for (int h = 0; h < 4; h++) {
        float inv = 1.f / den[h];
        float z0 = acc[h][0] * inv, z1 = acc[h][1] * inv;
        float z2 = acc[h][2] * inv, z3 = acc[h][3] * inv;
        bf16 h0, l0, h1, l1, h2, l2, h3, l3;
        split_bf16(z0, h0, l0); split_bf16(z1, h1, l1);
        split_bf16(z2, h2, l2); split_bf16(z3, h3, l3);
        __nv_bfloat162 hpA, hpB, lpA, lpB;
        hpA.x = h0; hpA.y = h1; hpB.x = h2; hpB.y = h3;
        lpA.x = l0; lpA.y = l1; lpB.x = l2; lpB.y = l3;
        *(__nv_bfloat162*)&g_Zp[rb + h * 256 + lane * 4]           = hpA;
        *(__nv_bfloat162*)&g_Zp[rb + h * 256 + lane * 4 + 2]       = hpB;
        *(__nv_bfloat162*)&g_Zp[rb + h * 256 + 128 + lane * 4]     = lpA;
        *(__nv_bfloat162*)&g_Zp[rb + h * 256 + 128 + lane * 4 + 2] = lpB;
    }
}

// ================= agg2: warp-per-node (standalone, R13 config) =================
__global__ void __launch_bounds__(256) k_agg2(const float* __restrict__ b2) {
    const int tid = threadIdx.x, wid = tid >> 5, lane = tid & 31;
    const int n = blockIdx.x * 8 + wid;
    const int beg = g_off[n], end = g_off[n + 1];

    const float adn = g_att2d[n];
    float acc[4] = {0.f, 0.f, 0.f, 0.f};
    float den = 0.f;

    for (int c0 = beg; c0 < end; c0 += 32) {
        const int m = min(32, end - c0);
        int   sj = 0;
        float ej = 0.f;
        if (lane < m) {
            sj = g_csrc[c0 + lane];
            ej = expf(lrelu02(g_att2s[sj] + adn));
        }
        const int mr = (m + 7) & ~7;
        for (int j0 = 0; j0 < mr; j0 += 8) {
#pragma unroll
            for (int jj = 0; jj < 8; jj++) {
                const int j = j0 + jj;
                int   s = __shfl_sync(0xffffffffu, sj, j);
                float w = __shfl_sync(0xffffffffu, ej, j);
                uint2 hv = *(const uint2*)&g_h2h[(size_t)s * 128 + lane * 4];
                float2 fa = __half22float2(*(const __half2*)&hv.x);
                float2 fb = __half22float2(*(const __half2*)&hv.y);
                den += w;
                acc[0] += w * fa.x; acc[1] += w * fa.y;
                acc[2] += w * fb.x; acc[3] += w * fb.y;
            }
        }
    }
    const float inv = 1.f / den;
    const float4 bv = *(const float4*)&b2[lane * 4];
    float o0 = eluf(acc[0] * inv + bv.x), o1 = eluf(acc[1] * inv + bv.y);
    float o2 = eluf(acc[2] * inv + bv.z), o3 = eluf(acc[3] * inv + bv.w);
    bf16 h0, l0, h1, l1, h2, l2, h3, l3;
    split_bf16(o0, h0, l0); split_bf16(o1, h1, l1);
    split_bf16(o2, h2, l2); split_bf16(o3, h3, l3);
    __nv_bfloat162 hpA, hpB, lpA, lpB;
    hpA.x = h0; hpA.y = h1; hpB.x = h2; hpB.y = h3;
    lpA.x = l0; lpA.y = l1; lpB.x = l2; lpB.y = l3;
    const size_t rb = (size_t)n * 256;
    *(__nv_bfloat162*)&g_tp[rb + lane * 4]           = hpA;
    *(__nv_bfloat162*)&g_tp[rb + lane * 4 + 2]       = hpB;
    *(__nv_bfloat162*)&g_tp[rb + 128 + lane * 4]     = lpA;
    *(__nv_bfloat162*)&g_tp[rb + 128 + lane * 4 + 2] = lpB;
}

// ================= 128-wide mma GEMM body, 4-stage pipeline =================
template <int ACT, int ATT>
__device__ __forceinline__ void mgemm_body(
    const bf16* __restrict__ Ap, const bf16* __restrict__ Bp,
    int K, int apitch, int bpitch, int Nn, int Wtot,
    const float* __restrict__ bias,
    float* __restrict__ Cf, __half* __restrict__ Ch, bf16* __restrict__ Cb2,
    const float* __restrict__ a_s, const float* __restrict__ a_d,
    float* __restrict__ atts, float* __restrict__ attd,
    int heads, int head, int row0, int col0, char* dyn)
{
    __shared__ float s_as[128], s_ad[128];
    const uint32_t dynu = smem_u32(dyn);

    const int tid = threadIdx.x;
    const int wid = tid >> 5, lane = tid & 31;
    const int g = lane >> 2, tig = lane & 3;
    const int warp_m = wid & 3, warp_n = wid >> 2;

    const int lrow = tid >> 1, lsel = tid & 1;
    const bf16* Agb = Ap + (size_t)(row0 + lrow) * apitch + lsel * K;
    const bf16* Bgb = Bp + (size_t)(col0 + lrow) * bpitch + lsel * K;
    const uint32_t soff = (uint32_t)lrow * 80u + (uint32_t)lsel * 32u;

    const int arow_l = (((lane >> 3) & 1) << 3) + (lane & 7);
    const int acol_l = (lane >> 4) << 3;
    const int brow_l = (lane & 7) + ((lane >> 4) << 3);
    const int bcol_l = ((lane >> 3) & 1) << 3;

    float c[2][8][4];
#pragma unroll
    for (int i = 0; i < 2; i++)
#pragma unroll
        for (int j = 0; j < 8; j++)
#pragma unroll
            for (int q = 0; q < 4; q++) c[i][j][q] = 0.f;

    const int NT = K >> 4;
#pragma unroll
    for (int p = 0; p < 3; p++) {
        if (p < NT) {
            const uint32_t st = dynu + (uint32_t)p * 20480u;
            const int koff = p * 16;
            cp_async16(st + soff, Agb + koff);
            cp_async16(st + soff + 16, Agb + koff + 8);
            cp_async16(st + 10240u + soff, Bgb + koff);
            cp_async16(st + 10240u + soff + 16, Bgb + koff + 8);
        }
        asm volatile("cp.async.commit_group;" ::: "memory");
    }

    for (int kt = 0; kt < NT; kt++) {
        const int rem = NT - 1 - kt;
        if (rem >= 2)      asm volatile("cp.async.wait_group 2;" ::: "memory");
        else if (rem == 1) asm volatile("cp.async.wait_group 1;" ::: "memory");
        else               asm volatile("cp.async.wait_group 0;" ::: "memory");
        __syncthreads();
        if (kt + 3 < NT) {
            const uint32_t st = dynu + (uint32_t)((kt + 3) & 3) * 20480u;
            const int koff = (kt + 3) * 16;
            cp_async16(st + soff, Agb + koff);
            cp_async16(st + soff + 16, Agb + koff + 8);
            cp_async16(st + 10240u + soff, Bgb + koff);
            cp_async16(st + 10240u + soff + 16, Bgb + koff + 8);
            asm volatile("cp.async.commit_group;" ::: "memory");
        }

        const uint32_t aBase = dynu + (uint32_t)(kt & 3) * 20480u;
        const uint32_t bBase = aBase + 10240u;

        uint32_t ah[2][4], al[2][4], bb[8][2];
#pragma unroll
        for (int mi = 0; mi < 2; mi++) {
            uint32_t r = aBase + (uint32_t)(warp_m * 32 + mi * 16 + arow_l) * 80u
                               + (uint32_t)acol_l * 2u;
            ldm_x4(ah[mi], r);
            ldm_x4(al[mi], r + 32u);
        }
#pragma unroll
        for (int p = 0; p < 4; p++) {
            uint32_t t[4];
            uint32_t r = bBase + (uint32_t)(warp_n * 64 + p * 16 + brow_l) * 80u
                               + (uint32_t)bcol_l * 2u;
            ldm_x4(t, r);
            bb[2 * p][0] = t[0]; bb[2 * p][1] = t[1];
            bb[2 * p + 1][0] = t[2]; bb[2 * p + 1][1] = t[3];
        }
#pragma unroll
        for (int mi = 0; mi < 2; mi++)
#pragma unroll
            for (int ni = 0; ni < 8; ni++)
                mma_bf16(c[mi][ni], ah[mi], bb[ni]);
#pragma unroll
        for (int mi = 0; mi < 2; mi++)
#pragma unroll
            for (int ni = 0; ni < 8; ni++)
                mma_bf16(c[mi][ni], al[mi], bb[ni]);
#pragma unroll
        for (int p = 0; p < 4; p++) {
            uint32_t t[4];
            uint32_t r = bBase + (uint32_t)(warp_n * 64 + p * 16 + brow_l) * 80u
                               + (uint32_t)bcol_l * 2u + 32u;
            ldm_x4(t, r);
            bb[2 * p][0] = t[0]; bb[2 * p][1] = t[1];
            bb[2 * p + 1][0] = t[2]; bb[2 * p + 1][1] = t[3];
        }
#pragma unroll
        for (int mi = 0; mi < 2; mi++)
#pragma unroll
            for (int ni = 0; ni < 8; ni++)
                mma_bf16(c[mi][ni], ah[mi], bb[ni]);
    }

    if (ATT) {
        __syncthreads();
        if (tid < 128) { s_as[tid] = 0.f; s_ad[tid] = 0.f; }
        __syncthreads();
    }

    float ssv[2][2] = {{0.f, 0.f}, {0.f, 0.f}};
    float sdv[2][2] = {{0.f, 0.f}, {0.f, 0.f}};

#pragma unroll
    for (int ni = 0; ni < 8; ni++) {
        const int cA = col0 + warp_n * 64 + ni * 8 + tig * 2;
        float b0 = 0.f, b1 = 0.f;
        if (bias) { b0 = __ldg(&bias[cA]); b1 = __ldg(&bias[cA + 1]); }
        float asA = 0.f, asB = 0.f, adA = 0.f, adB = 0.f;
        if (ATT) {
            asA = __ldg(&a_s[cA]); asB = __ldg(&a_s[cA + 1]);
            adA = __ldg(&a_d[cA]); adB = __ldg(&a_d[cA + 1]);
        }
#pragma unroll
        for (int mi = 0; mi < 2; mi++) {
            const int r0g = row0 + warp_m * 32 + mi * 16 + g;
            const int r1g = r0g + 8;
            float v00 = c[mi][ni][0] + b0, v01 = c[mi][ni][1] + b1;
            float v10 = c[mi][ni][2] + b0, v11 = c[mi][ni][3] + b1;
            if (ACT == 2) {
                v00 = eluf(v00); v01 = eluf(v01);
                v10 = eluf(v10); v11 = eluf(v11);
            }
            if (ATT) {
                ssv[mi][0] += v00 * asA + v01 * asB;
                ssv[mi][1] += v10 * asA + v11 * asB;
                sdv[mi][0] += v00 * adA + v01 * adB;
                sdv[mi][1] += v10 * adA + v11 * adB;
            }
            if (Cf) {
                *(float2*)&Cf[(size_t)r0g * Nn + cA] = make_float2(v00, v01);
                *(float2*)&Cf[(size_t)r1g * Nn + cA] = make_float2(v10, v11);
            }
            if (Ch) {
                *(__half2*)&Ch[(size_t)r0g * Nn + cA] = __floats2half2_rn(v00, v01);
                *(__half2*)&Ch[(size_t)r1g * Nn + cA] = __floats2half2_rn(v10, v11);
            }
            if (Cb2) {
                bf16 h0, l0, h1, l1;
                __nv_bfloat162 hp, lp;
                size_t rb0 = (size_t)r0g * 2 * Wtot;
                split_bf16(v00, h0, l0); split_bf16(v01, h1, l1);
                hp.x = h0; hp.y = h1; lp.x = l0; lp.y = l1;
                *(__nv_bfloat162*)&Cb2[rb0 + cA]        = hp;
                *(__nv_bfloat162*)&Cb2[rb0 + Wtot + cA] = lp;
                size_t rb1 = (size_t)r1g * 2 * Wtot;
                split_bf16(v10, h0, l0); split_bf16(v11, h1, l1);
                hp.x = h0; hp.y = h1; lp.x = l0; lp.y = l1;
                *(__nv_bfloat162*)&Cb2[rb1 + cA]        = hp;
                *(__nv_bfloat162*)&Cb2[rb1 + Wtot + cA] = lp;
            }
        }
    }

    if (ATT) {
#pragma unroll
        for (int mi = 0; mi < 2; mi++) {
            const int rl0 = warp_m * 32 + mi * 16 + g;
            atomicAdd(&s_as[rl0], ssv[mi][0]);
            atomicAdd(&s_as[rl0 + 8], ssv[mi][1]);
            atomicAdd(&s_ad[rl0], sdv[mi][0]);
            atomicAdd(&s_ad[rl0 + 8], sdv[mi][1]);
        }
        __syncthreads();
        if (tid < 128) {
            const int row = row0 + tid;
            atts[row * heads + head] = s_as[tid];
            attd[row * heads + head] = s_ad[tid];
        }
    }
}

__global__ void __launch_bounds__(256) k_gemmZ(const float* __restrict__ b1) {
    extern __shared__ char dyn[];
    const int head = blockIdx.x;
    mgemm_body<2, 0>(g_Zp + head * 256, g_W1t, 128, 1024, 256, 512, 512,
                     b1, nullptr, nullptr, g_e1p,
                     nullptr, nullptr, nullptr, nullptr,
                     1, 0, blockIdx.y * 128, head * 128, dyn);
}
__global__ void __launch_bounds__(256) k_mgemm2(const float* __restrict__ as2,
                                                const float* __restrict__ ad2) {
    extern __shared__ char dyn[];
    mgemm_body<0, 1>(g_e1p, g_W2t, 512, 1024, 1024, 128, 0,
                     nullptr, nullptr, g_h2h, nullptr,
                     as2, ad2, g_att2s, g_att2d,
                     1, 0, blockIdx.x * 128, 0, dyn);
}

// ================= fused node MLP (R13 config) =================
template <int AFROM>
__device__ __forceinline__ void gemm_stage(
    float (&c)[2][8][4],
    const bf16* Agb, const bf16* Bgb,
    uint32_t aChunkBase, uint32_t sAs, uint32_t sBs, uint32_t soff,
    int warp_m, int warp_n, int arow_l, int acol_l, int brow_l, int bcol_l)
{
#pragma unroll
    for (int i = 0; i < 2; i++)
#pragma unroll
        for (int j = 0; j < 8; j++)
#pragma unroll
            for (int q = 0; q < 4; q++) c[i][j][q] = 0.f;

    if (AFROM == 0) { cp_async16(sAs + soff, Agb); cp_async16(sAs + soff + 16, Agb + 8); }
    cp_async16(sBs + soff, Bgb);
    cp_async16(sBs + soff + 16, Bgb + 8);
    asm volatile("cp.async.commit_group;" ::: "memory");

#pragma unroll
    for (int kt = 0; kt < 8; kt++) {
        const int buf = kt & 1;
        if (kt + 1 < 8) {
            const int koff = (kt + 1) * 16;
            const uint32_t bofs = ((kt + 1) & 1) ? 10240u : 0u;
            if (AFROM == 0) {
                cp_async16(sAs + bofs + soff, Agb + koff);
                cp_async16(sAs + bofs + soff + 16, Agb + koff + 8);
            }
            cp_async16(sBs + bofs + soff, Bgb + koff);
            cp_async16(sBs + bofs + soff + 16, Bgb + koff + 8);
            asm volatile("cp.async.commit_group;" ::: "memory");
            asm volatile("cp.async.wait_group 1;" ::: "memory");
        } else {
            asm volatile("cp.async.wait_group 0;" ::: "memory");
        }
        __syncthreads();
        const uint32_t aBase = (AFROM == 0) ? (sAs + (uint32_t)buf * 10240u)
                                            : (aChunkBase + (uint32_t)kt * 10240u);
        const uint32_t bBase = sBs + (uint32_t)buf * 10240u;

        uint32_t ah[2][4], al[2][4], bb[8][2];
#pragma unroll
        for (int mi = 0; mi < 2; mi++) {
            uint32_t r = aBase + (uint32_t)(warp_m * 32 + mi * 16 + arow_l) * 80u
                               + (uint32_t)acol_l * 2u;
            ldm_x4(ah[mi], r);
            ldm_x4(al[mi], r + 32u);
        }
#pragma unroll
        for (int p = 0; p < 4; p++) {
            uint32_t t[4];
            uint32_t r = bBase + (uint32_t)(warp_n * 64 + p * 16 + brow_l) * 80u
                               + (uint32_t)bcol_l * 2u;
            ldm_x4(t, r);
            bb[2 * p][0] = t[0]; bb[2 * p][1] = t[1];
            bb[2 * p + 1][0] = t[2]; bb[2 * p + 1][1] = t[3];
        }
#pragma unroll
        for (int mi = 0; mi < 2; mi++)
#pragma unroll
            for (int ni = 0; ni < 8; ni++)
                mma_bf16(c[mi][ni], ah[mi], bb[ni]);
#pragma unroll
        for (int mi = 0; mi < 2; mi++)
#pragma unroll
            for (int ni = 0; ni < 8; ni++)
                mma_bf16(c[mi][ni], al[mi], bb[ni]);
#pragma unroll
        for (int p = 0; p < 4; p++) {
            uint32_t t[4];
            uint32_t r = bBase + (uint32_t)(warp_n * 64 + p * 16 + brow_l) * 80u
                               + (uint32_t)bcol_l * 2u + 32u;
            ldm_x4(t, r);
            bb[2 * p][0] = t[0]; bb[2 * p][1] = t[1];
            bb[2 * p + 1][0] = t[2]; bb[2 * p + 1][1] = t[3];
        }
#pragma unroll
        for (int mi = 0; mi < 2; mi++)
#pragma unroll
            for (int ni = 0; ni < 8; ni++)
                mma_bf16(c[mi][ni], ah[mi], bb[ni]);
        __syncthreads();
    }
}

__device__ __forceinline__ void store_split(char* base, int row, int col, float v0, float v1) {
    bf16 h0, l0, h1, l1;
    split_bf16(v0, h0, l0);
    split_bf16(v1, h1, l1);
    char* p = base + (col >> 4) * 10240 + row * 80 + (col & 15) * 2;
    __nv_bfloat162 hp, lp;
    hp.x = h0; hp.y = h1; lp.x = l0; lp.y = l1;
    *(__nv_bfloat162*)p = hp;
    *(__nv_bfloat162*)(p + 32) = lp;
}

__global__ void __launch_bounds__(256) k_nodeMLP(const float* __restrict__ bo1,
                                                 const float* __restrict__ bo2,
                                                 float* __restrict__ xo,
                                                 __half* __restrict__ PQh) {
    extern __shared__ char dyn[];
    char* uspC = dyn;
    char* xspC = dyn + 81920;
    const uint32_t dynu = smem_u32(dyn);
    const uint32_t uspU = dynu;
    const uint32_t xspU = dynu + 81920u;
    const uint32_t sAs  = dynu + 163840u;
    const uint32_t sBs  = dynu + 184320u;

    const int tid = threadIdx.x;
    const int wid = tid >> 5, lane = tid & 31;
    const int g = lane >> 2, tig = lane & 3;
    const int warp_m = wid & 3, warp_n = wid >> 2;
    const int row0 = blockIdx.x * 128;
    const int lrow = tid >> 1, lsel = tid & 1;
    const uint32_t soff = (uint32_t)lrow * 80u + (uint32_t)lsel * 32u;
    const int arow_l = (((lane >> 3) & 1) << 3) + (lane & 7);
    const int acol_l = (lane >> 4) << 3;
    const int brow_l = (lane & 7) + ((lane >> 4) << 3);
    const int bcol_l = ((lane >> 3) & 1) << 3;

    float c[2][8][4];

    {
        const bf16* Agb = g_tp + (size_t)(row0 + lrow) * 256 + lsel * 128;
        const bf16* Bgb = g_Wo1t + (size_t)lrow * 256 + lsel * 128;
        gemm_stage<0>(c, Agb, Bgb, 0u, sAs, sBs, soff,
                      warp_m, warp_n, arow_l, acol_l, brow_l, bcol_l);
#pragma unroll
        for (int ni = 0; ni < 8; ni++) {
            const int col = warp_n * 64 + ni * 8 + tig * 2;
            const float b0 = __ldg(&bo1[col]), b1 = __ldg(&bo1[col + 1]);
#pragma unroll
            for (int mi = 0; mi < 2; mi++) {
                const int r0l = warp_m * 32 + mi * 16 + g;
                store_split(uspC, r0l, col,
                            fmaxf(c[mi][ni][0] + b0, 0.f), fmaxf(c[mi][ni][1] + b1, 0.f));
                store_split(uspC, r0l + 8, col,
                            fmaxf(c[mi][ni][2] + b0, 0.f), fmaxf(c[mi][ni][3] + b1, 0.f));
            }
        }
        __syncthreads();
    }

    {
        const bf16* Bgb = g_Wo2t + (size_t)lrow * 256 + lsel * 128;
        gemm_stage<1>(c, nullptr, Bgb, uspU, sAs, sBs, soff,
                      warp_m, warp_n, arow_l, acol_l, brow_l, bcol_l);
#pragma unroll
        for (int ni = 0; ni < 8; ni++) {
            const int col = warp_n * 64 + ni * 8 + tig * 2;
            const float b0 = __ldg(&bo2[col]), b1 = __ldg(&bo2[col + 1]);
#pragma unroll
            for (int mi = 0; mi < 2; mi++) {
                const int r0l = warp_m * 32 + mi * 16 + g;
                const int r1l = r0l + 8;
                float v00 = c[mi][ni][0] + b0, v01 = c[mi][ni][1] + b1;
                float v10 = c[mi][ni][2] + b0, v11 = c[mi][ni][3] + b1;
                *(float2*)&xo[(size_t)(row0 + r0l) * 128 + col] = make_float2(v00, v01);
                *(float2*)&xo[(size_t)(row0 + r1l) * 128 + col] = make_float2(v10, v11);
                store_split(xspC, r0l, col, v00, v01);
                store_split(xspC, r1l, col, v10, v11);
            }
        }
        __syncthreads();
    }

#pragma unroll
    for (int p = 0; p < 2; p++) {
        const bf16* Bgb = g_WePQt + (size_t)(p * 128 + lrow) * 256 + lsel * 128;
        gemm_stage<1>(c, nullptr, Bgb, xspU, sAs, sBs, soff,
                      warp_m, warp_n, arow_l, acol_l, brow_l, bcol_l);
#pragma unroll
        for (int ni = 0; ni < 8; ni++) {
            const int col = warp_n * 64 + ni * 8 + tig * 2;
            const int gcol = p * 128 + col;
            const float b0 = g_bePQ[gcol], b1 = g_bePQ[gcol + 1];
#pragma unroll
            for (int mi = 0; mi < 2; mi++) {
                const int r0g = row0 + warp_m * 32 + mi * 16 + g;
                const int r1g = r0g + 8;
                *(__half2*)&PQh[(size_t)r0g * 256 + gcol] =
                    __floats2half2_rn(c[mi][ni][0] + b0, c[mi][ni][1] + b1);
                *(__half2*)&PQh[(size_t)r1g * 256 + gcol] =
                    __floats2half2_rn(c[mi][ni][2] + b0, c[mi][ni][3] + b1);
            }
        }
    }
}

// ================= edge MLP v3: 128 edges/block =================
__global__ void __launch_bounds__(256) k_edge_final(const void* __restrict__ ei,
                                                    const float* __restrict__ eattr,
                                                    const float* __restrict__ We1,
                                                    const float* __restrict__ We2,
                                                    const float* __restrict__ be2,
                                                    float* __restrict__ out) {
    __shared__ float  sW1f[16 * 128];
    __shared__ __half sHid[128][136];
    __shared__ __half sW2h[16][136];
    const int tid = threadIdx.x, wid = tid >> 5, lane = tid & 31;

    for (int i = tid; i < 2048; i += 256) {
        sW1f[i] = We1[256 * 128 + i];
        int cc = i >> 4, o = i & 15;
        sW2h[o][cc] = __float2half(We2[i]);
    }
    __syncthreads();

    float4 w1r[16];
#pragma unroll
    for (int k = 0; k < 16; k++) w1r[k] = *(const float4*)&sW1f[k * 128 + lane * 4];

    const int is64 = g_is64;
    const long e0 = (long)blockIdx.x * 128;

#pragma unroll
    for (int r = 0; r < 16; r++) {
        const long e = e0 + wid * 16 + r;
        int s = idx_at(ei, e, is64);
        int d = idx_at(ei, (long)EE + e, is64);
        uint2 pv = *(const uint2*)&g_PQh[(size_t)s * 256 + lane * 4];
        uint2 qv = *(const uint2*)&g_PQh[(size_t)d * 256 + 128 + lane * 4];
        float2 pa = __half22float2(*(const __half2*)&pv.x);
        float2 pb = __half22float2(*(const __half2*)&pv.y);
        float2 qa = __half22float2(*(const __half2*)&qv.x);
        float2 qb = __half22float2(*(const __half2*)&qv.y);
        float4 hv;
        hv.x = pa.x + qa.x; hv.y = pa.y + qa.y;
        hv.z = pb.x + qb.x; hv.w = pb.y + qb.y;
        float eav = (lane < 16) ? eattr[e * 16 + lane] : 0.f;
#pragma unroll
        for (int k = 0; k < 16; k++) {
            float ek = __shfl_sync(0xffffffffu, eav, k);
            hv.x += ek * w1r[k].x; hv.y += ek * w1r[k].y;
            hv.z += ek * w1r[k].z; hv.w += ek * w1r[k].w;
        }
        __half2 h01 = __floats2half2_rn(fmaxf(hv.x, 0.f), fmaxf(hv.y, 0.f));
        __half2 h23 = __floats2half2_rn(fmaxf(hv.z, 0.f), fmaxf(hv.w, 0.f));
        uint2 packed;
        packed.x = *(uint32_t*)&h01;
        packed.y = *(uint32_t*)&h23;
        *(uint2*)&sHid[wid * 16 + r][lane * 4] = packed;
    }
    __syncthreads();

    {
        const int g = lane >> 2, tig = lane & 3;
        const int arow_l = (((lane >> 3) & 1) << 3) + (lane & 7);
        const int acol_l = (lane >> 4) << 3;
        const int brow_l = (lane & 7) + ((lane >> 4) << 3);
        const int bcol_l = ((lane >> 3) & 1) << 3;
        const uint32_t sA = smem_u32(&sHid[wid * 16][0]);
        const uint32_t sB = smem_u32(&sW2h[0][0]);

        float c0[4] = {0.f, 0.f, 0.f, 0.f};
        float c1[4] = {0.f, 0.f, 0.f, 0.f};
#pragma unroll
        for (int kk = 0; kk < 128; kk += 16) {
            uint32_t af[4], bfr[4];
            ldm_x4(af, sA + (uint32_t)arow_l * 272u + (uint32_t)(kk + acol_l) * 2u);
            ldm_x4(bfr, sB + (uint32_t)brow_l * 272u + (uint32_t)(kk + bcol_l) * 2u);
            mma_f16(c0, af, bfr);
            mma_f16(c1, af, bfr + 2);
        }

        const long eA = e0 + wid * 16 + g;
        const long eB = eA + 8;
        const float b0 = __ldg(&be2[tig * 2]),     b1 = __ldg(&be2[tig * 2 + 1]);
        const float b8 = __ldg(&be2[8 + tig * 2]), b9 = __ldg(&be2[8 + tig * 2 + 1]);
        *(float2*)&out[eA * 16 + tig * 2]     = make_float2(c0[0] + b0, c0[1] + b1);
        *(float2*)&out[eB * 16 + tig * 2]     = make_float2(c0[2] + b0, c0[3] + b1);
        *(float2*)&out[eA * 16 + 8 + tig * 2] = make_float2(c1[0] + b8, c1[1] + b9);
        *(float2*)&out[eB * 16 + 8 + tig * 2] = make_float2(c1[2] + b8, c1[3] + b9);
    }
}

// ================= launcher =================
extern "C" void kernel_launch(void* const* d_in, const int* in_sizes, int n_in,
                              void* d_out, int out_size) {
    const float* x    = (const float*)d_in[0];
    const void*  ei   = d_in[1];
    const float* eatt = (const float*)d_in[2];
    const float* W1   = (const float*)d_in[3];
    const float* as1  = (const float*)d_in[4];
    const float* ad1  = (const float*)d_in[5];
    const float* b1   = (const float*)d_in[6];
    const float* W2   = (const float*)d_in[7];
    const float* as2  = (const float*)d_in[8];
    const float* ad2  = (const float*)d_in[9];
    const float* b2   = (const float*)d_in[10];
    const float* Wo1  = (const float*)d_in[11];
    const float* bo1  = (const float*)d_in[12];
    const float* Wo2  = (const float*)d_in[13];
    const float* bo2  = (const float*)d_in[14];
    const float* We1  = (const float*)d_in[15];
    const float* be1  = (const float*)d_in[16];
    const float* We2  = (const float*)d_in[17];
    const float* be2  = (const float*)d_in[18];

    float* out  = (float*)d_out;
    float* xo   = out;
    float* eout = out + (size_t)NN * 128;

    __half* PQh;
    cudaGetSymbolAddress((void**)&PQh, g_PQh);

    cudaFuncSetAttribute(k_gemmZ, cudaFuncAttributeMaxDynamicSharedMemorySize, 81920);
    cudaFuncSetAttribute(k_mgemm2, cudaFuncAttributeMaxDynamicSharedMemorySize, 81920);
    cudaFuncSetAttribute(k_nodeMLP, cudaFuncAttributeMaxDynamicSharedMemorySize, 204800);

    // 0: prep = xh (vectorized) | convW | init | va
    k_prep<<<4899, 256>>>(x, (const int*)ei, W1, W2, Wo1, Wo2, We1, be1, as1, ad1);
    // 1: hist | attdot (fused)
    k_histdot<<<2125 + 4000, 256>>>(ei);
    // 2: scan
    k_scan_all<<<1, 1024>>>();
    // 3: scatter
    k_scatter<<<2125, 256>>>(ei);
    // 4: agg1x
    k_agg1x<<<4000, 256>>>();
    // 5: gemmZ
    k_gemmZ<<<dim3(4, 250), 256, 81920>>>(b1);
    // 6: gemm2
    k_mgemm2<<<250, 256, 81920>>>(as2, ad2);
    // 7: agg2 (standalone, high occupancy)
    k_agg2<<<4000, 256>>>(b2);
    // 8: node MLP
    k_nodeMLP<<<250, 256, 204800>>>(bo1, bo2, xo, PQh);
    // 9: edge MLP v3
    k_edge_final<<<EE / 128, 256>>>(ei, eatt, We1, We2, be2, eout);
}

// round 16
// speedup vs baseline: 1.0949x; 1.0019x over previous
#include <cuda_runtime.h>
#include <cuda_bf16.h>
#include <cuda_fp16.h>
#include <cstdint>

#define NN 32000
#define EE 512000
#define ET (EE + NN)
#define DD 128
#define HH 4
#define EAD 16

typedef __nv_bfloat16 bf16;

// ================= scratch =================
__device__ int   g_is64;
__device__ int   g_deg[NN];
__device__ int   g_off[NN + 1];
__device__ int   g_cur[NN];
__device__ int   g_csrc[ET];

__device__ __half g_xh [(size_t)NN * 128];
__device__ __half g_h2h[(size_t)NN * 128];
__device__ __half g_PQh[(size_t)NN * 256];
__device__ float g_att1s[NN * 4];
__device__ float g_att1d[NN * 4];
__device__ float g_att2s[NN];
__device__ float g_att2d[NN];
__device__ float g_bePQ[256];
__device__ float g_va[8 * 128];

__device__ bf16  g_Zp [(size_t)NN * 1024];
__device__ bf16  g_e1p[(size_t)NN * 1024];
__device__ bf16  g_tp [(size_t)NN * 256];
__device__ bf16  g_W1t  [512 * 256];
__device__ bf16  g_W2t  [128 * 1024];
__device__ bf16  g_Wo1t [128 * 256];
__device__ bf16  g_Wo2t [128 * 256];
__device__ bf16  g_WePQt[256 * 256];

// ================= helpers =================
__device__ __forceinline__ float lrelu02(float a) { return a > 0.f ? a : 0.2f * a; }
__device__ __forceinline__ float eluf(float v)    { return v > 0.f ? v : expm1f(v); }
__device__ __forceinline__ int idx_at(const void* ei, long pos, int is64) {
    if (is64) return (int)((const long long*)ei)[pos];
    return ((const int*)ei)[pos];
}
__device__ __forceinline__ void split_bf16(float v, bf16& h, bf16& l) {
    h = __float2bfloat16(v);
    l = __float2bfloat16(v - __bfloat162float(h));
}
__device__ __forceinline__ uint32_t smem_u32(const void* p) {
    uint32_t a;
    asm("{ .reg .u64 t; cvta.to.shared.u64 t, %1; cvt.u32.u64 %0, t; }" : "=r"(a) : "l"(p));
    return a;
}
__device__ __forceinline__ void cp_async16(uint32_t saddr, const void* g) {
    asm volatile("cp.async.cg.shared.global [%0], [%1], 16;" :: "r"(saddr), "l"(g));
}
__device__ __forceinline__ void mma_bf16(float* c, const uint32_t* a, const uint32_t* b) {
    asm volatile(
        "mma.sync.aligned.m16n8k16.row.col.f32.bf16.bf16.f32 "
        "{%0,%1,%2,%3}, {%4,%5,%6,%7}, {%8,%9}, {%0,%1,%2,%3};"
        : "+f"(c[0]), "+f"(c[1]), "+f"(c[2]), "+f"(c[3])
        : "r"(a[0]), "r"(a[1]), "r"(a[2]), "r"(a[3]), "r"(b[0]), "r"(b[1]));
}
__device__ __forceinline__ void mma_f16(float* c, const uint32_t* a, const uint32_t* b) {
    asm volatile(
        "mma.sync.aligned.m16n8k16.row.col.f32.f16.f16.f32 "
        "{%0,%1,%2,%3}, {%4,%5,%6,%7}, {%8,%9}, {%0,%1,%2,%3};"
        : "+f"(c[0]), "+f"(c[1]), "+f"(c[2]), "+f"(c[3])
        : "r"(a[0]), "r"(a[1]), "r"(a[2]), "r"(a[3]), "r"(b[0]), "r"(b[1]));
}
__device__ __forceinline__ void ldm_x4(uint32_t* r, uint32_t addr) {
    asm volatile("ldmatrix.sync.aligned.m8n8.x4.shared.b16 {%0,%1,%2,%3}, [%4];"
                 : "=r"(r[0]), "=r"(r[1]), "=r"(r[2]), "=r"(r[3]) : "r"(addr));
}

// ================= prep: xh (vectorized) | convW | init | va =================
__device__ __forceinline__ void conv_emit(const float* W, bf16* Wt, int K, int N, int idx) {
    int n = idx / K;
    int k = idx - n * K;
    bf16 h, l;
    split_bf16(W[(size_t)k * N + n], h, l);
    bf16* row = Wt + (size_t)n * 2 * K;
    row[k] = h; row[K + k] = l;
}
__global__ void __launch_bounds__(256) k_prep(const float* x, const int* eiw,
                                              const float* W1, const float* W2,
                                              const float* Wo1, const float* Wo2,
                                              const float* We1, const float* be1,
                                              const float* as1, const float* ad1) {
    const int b = blockIdx.x, tid = threadIdx.x;
    if (b < 4000) {
        long i4 = ((long)b * 256 + tid) * 4;
        float4 v = *(const float4*)&x[i4];
        *(__half2*)&g_xh[i4]     = __floats2half2_rn(v.x, v.y);
        *(__half2*)&g_xh[i4 + 2] = __floats2half2_rn(v.z, v.w);
    } else if (b < 4770) {
        int i = (b - 4000) * 256 + tid;
        if (i < 65536)          conv_emit(W1,  g_W1t,  128, 512, i);
        else if (i < 131072)    conv_emit(W2,  g_W2t,  512, 128, i - 65536);
        else if (i < 147456)    conv_emit(Wo1, g_Wo1t, 128, 128, i - 131072);
        else if (i < 163840)    conv_emit(Wo2, g_Wo2t, 128, 128, i - 147456);
        else if (i < 180224)    conv_emit(We1, g_WePQt, 128, 128, i - 163840);
        else if (i < 196608)    conv_emit(We1 + 128 * 128, g_WePQt + 128 * 256, 128, 128, i - 180224);
        else if (i < 196864) {
            int j = i - 196608;
            g_bePQ[j] = (j < 128) ? be1[j] : 0.f;
        }
    } else if (b < 4895) {
        int i = (b - 4770) * 256 + tid;
        g_deg[i] = 0;
        if (b == 4770) {
            __shared__ int s_any;
            if (tid == 0) s_any = 0;
            __syncthreads();
            int any = 0;
            for (int j = tid; j < 1024; j += 256) any |= eiw[2 * j + 1];
            if (any) atomicOr(&s_any, 1);
            __syncthreads();
            if (tid == 0) g_is64 = (s_any == 0) ? 1 : 0;
        }
    } else {
        int v = (b - 4895) * 2 + (tid >> 7);
        int k = tid & 127;
        const float* a = (v < 4) ? (as1 + v * 128) : (ad1 + (v - 4) * 128);
        int hh = (v < 4) ? v : (v - 4);
        const float* wrow = W1 + (size_t)k * 512 + hh * 128;
        float s = 0.f;
#pragma unroll 4
        for (int c = 0; c < 128; c++) s += wrow[c] * a[c];
        g_va[v * 128 + k] = s;
    }
}

// ================= fused hist | attdot (hist: 4 edges/thread, coalesced) =========
#define HBLK 532   // 532 * 1024 = 544,768 >= ET
__global__ void __launch_bounds__(256) k_histdot(const void* ei) {
    const int b = blockIdx.x, tid = threadIdx.x;
    if (b < HBLK) {
        const int is64 = g_is64;
        const long base = (long)b * 1024 + tid;
#pragma unroll
        for (int q = 0; q < 4; q++) {
            const long e = base + q * 256;
            if (e < ET) {
                int d = (e < EE) ? idx_at(ei, (long)EE + e, is64) : (int)(e - EE);
                atomicAdd(&g_deg[d], 1);
            }
        }
    } else {
        __shared__ float sva[1024];
        for (int i = tid; i < 1024; i += 256) sva[i] = g_va[i];
        __syncthreads();
        const int w = tid >> 5, lane = tid & 31;
        const int n = (b - HBLK) * 8 + w;
        uint2 xv2 = *(const uint2*)&g_xh[(size_t)n * 128 + lane * 4];
        float2 xa = __half22float2(*(const __half2*)&xv2.x);
        float2 xb = __half22float2(*(const __half2*)&xv2.y);
        float dots[8];
#pragma unroll
        for (int v = 0; v < 8; v++) {
            float4 vv = *(const float4*)&sva[v * 128 + lane * 4];
            dots[v] = xa.x * vv.x + xa.y * vv.y + xb.x * vv.z + xb.y * vv.w;
        }
#pragma unroll
        for (int off = 16; off; off >>= 1)
#pragma unroll
            for (int v = 0; v < 8; v++)
                dots[v] += __shfl_xor_sync(0xffffffffu, dots[v], off);
        if (lane < 4)      g_att1s[n * 4 + lane] = dots[lane];
        else if (lane < 8) g_att1d[n * 4 + lane - 4] = dots[lane];
    }
}

__global__ void __launch_bounds__(1024) k_scan_all() {
    __shared__ int wsum[32];
    const int t = threadIdx.x, lane = t & 31, w = t >> 5;
    const int base = t * 32;
    int loc[32];
    int s = 0;
    if (base < NN) {
#pragma unroll
        for (int i = 0; i < 8; i++) {
            int4 v = *(const int4*)&g_deg[base + i * 4];
            loc[i * 4 + 0] = v.x; loc[i * 4 + 1] = v.y;
            loc[i * 4 + 2] = v.z; loc[i * 4 + 3] = v.w;
            s += v.x + v.y + v.z + v.w;
        }
    }
    int inc = s;
#pragma unroll
    for (int off = 1; off < 32; off <<= 1) {
        int xx = __shfl_up_sync(0xffffffffu, inc, off);
        if (lane >= off) inc += xx;
    }
    if (lane == 31) wsum[w] = inc;
    __syncthreads();
    if (w == 0) {
        int v = wsum[lane];
        int vi = v;
#pragma unroll
        for (int off = 1; off < 32; off <<= 1) {
            int xx = __shfl_up_sync(0xffffffffu, vi, off);
            if (lane >= off) vi += xx;
        }
        wsum[lane] = vi;
    }
    __syncthreads();
    const int warpoff = (w == 0) ? 0 : wsum[w - 1];
    int run = warpoff + inc - s;
    if (base < NN) {
#pragma unroll
        for (int i = 0; i < 32; i++) {
            g_off[base + i] = run;
            g_cur[base + i] = run;
            run += loc[i];
        }
    }
    if (t == 0) g_off[NN] = wsum[31];
}

// scatter: 4 edges/thread, strided by 256 for coalescing
__global__ void __launch_bounds__(256) k_scatter(const void* ei) {
    const int is64 = g_is64;
    const long base = (long)blockIdx.x * 1024 + threadIdx.x;
#pragma unroll
    for (int q = 0; q < 4; q++) {
        const long e = base + q * 256;
        if (e < ET) {
            int s, d;
            if (e < EE) {
                s = idx_at(ei, e, is64);
                d = idx_at(ei, (long)EE + e, is64);
            } else {
                s = d = (int)(e - EE);
            }
            int pos = atomicAdd(&g_cur[d], 1);
            g_csrc[pos] = s;
        }
    }
}

// ================= agg1x: warp-per-node =================
__global__ void __launch_bounds__(256) k_agg1x() {
    const int tid = threadIdx.x, wid = tid >> 5, lane = tid & 31;
    const int n = blockIdx.x * 8 + wid;
    const int beg = g_off[n], end = g_off[n + 1];

    const float4 ad = *(const float4*)&g_att1d[n * 4];
    float acc[4][4];
#pragma unroll
    for (int h = 0; h < 4; h++)
#pragma unroll
        for (int q = 0; q < 4; q++) acc[h][q] = 0.f;
    float den[4] = {0.f, 0.f, 0.f, 0.f};

    for (int c0 = beg; c0 < end; c0 += 32) {
        const int m = min(32, end - c0);
        int   sj = 0;
        float4 e4 = make_float4(0.f, 0.f, 0.f, 0.f);
        if (lane < m) {
            sj = g_csrc[c0 + lane];
            float4 as = *(const float4*)&g_att1s[sj * 4];
            e4.x = expf(lrelu02(as.x + ad.x));
            e4.y = expf(lrelu02(as.y + ad.y));
            e4.z = expf(lrelu02(as.z + ad.z));
            e4.w = expf(lrelu02(as.w + ad.w));
        }
        const int mr = (m + 7) & ~7;
        for (int j0 = 0; j0 < mr; j0 += 8) {
#pragma unroll
            for (int jj = 0; jj < 8; jj++) {
                const int j = j0 + jj;
                int   s  = __shfl_sync(0xffffffffu, sj,  j);
                float w0 = __shfl_sync(0xffffffffu, e4.x, j);
                float w1 = __shfl_sync(0xffffffffu, e4.y, j);
                float w2 = __shfl_sync(0xffffffffu, e4.z, j);
                float w3 = __shfl_sync(0xffffffffu, e4.w, j);
                uint2 xv = *(const uint2*)&g_xh[(size_t)s * 128 + lane * 4];
                float2 fa = __half22float2(*(const __half2*)&xv.x);
                float2 fb = __half22float2(*(const __half2*)&xv.y);
                den[0] += w0; den[1] += w1; den[2] += w2; den[3] += w3;
                acc[0][0] += w0 * fa.x; acc[0][1] += w0 * fa.y; acc[0][2] += w0 * fb.x; acc[0][3] += w0 * fb.y;
                acc[1][0] += w1 * fa.x; acc[1][1] += w1 * fa.y; acc[1][2] += w1 * fb.x; acc[1][3] += w1 * fb.y;
                acc[2][0] += w2 * fa.x; acc[2][1] += w2 * fa.y; acc[2][2] += w2 * fb.x; acc[2][3] += w2 * fb.y;
                acc[3][0] += w3 * fa.x; acc[3][1] += w3 * fa.y; acc[3][2] += w3 * fb.x; acc[3][3] += w3 * fb.y;
            }
        }
    }
    const size_t rb = (size_t)n * 1024;
#pragma unroll
    for (int h = 0; h < 4; h++) {
        float inv = 1.f / den[h];
        float z0 = acc[h][0] * inv, z1 = acc[h][1] * inv;
        float z2 = acc[h][2] * inv, z3 = acc[h][3] * inv;
        bf16 h0, l0, h1, l1, h2, l2, h3, l3;
        split_bf16(z0, h0, l0); split_bf16(z1, h1, l1);
        split_bf16(z2, h2, l2); split_bf16(z3, h3, l3);
        __nv_bfloat162 hpA, hpB, lpA, lpB;
        hpA.x = h0; hpA.y = h1; hpB.x = h2; hpB.y = h3;
        lpA.x = l0; lpA.y = l1; lpB.x = l2; lpB.y = l3;
        *(__nv_bfloat162*)&g_Zp[rb + h * 256 + lane * 4]           = hpA;
        *(__nv_bfloat162*)&g_Zp[rb + h * 256 + lane * 4 + 2]       = hpB;
        *(__nv_bfloat162*)&g_Zp[rb + h * 256 + 128 + lane * 4]     = lpA;
        *(__nv_bfloat162*)&g_Zp[rb + h * 256 + 128 + lane * 4 + 2] = lpB;
    }
}

// ================= agg2: warp-per-node =================
__global__ void __launch_bounds__(256) k_agg2(const float* __restrict__ b2) {
    const int tid = threadIdx.x, wid = tid >> 5, lane = tid & 31;
    const int n = blockIdx.x * 8 + wid;
    const int beg = g_off[n], end = g_off[n + 1];

    const float adn = g_att2d[n];
    float acc[4] = {0.f, 0.f, 0.f, 0.f};
    float den = 0.f;

    for (int c0 = beg; c0 < end; c0 += 32) {
        const int m = min(32, end - c0);
        int   sj = 0;
        float ej = 0.f;
        if (lane < m) {
            sj = g_csrc[c0 + lane];
            ej = expf(lrelu02(g_att2s[sj] + adn));
        }
        const int mr = (m + 7) & ~7;
        for (int j0 = 0; j0 < mr; j0 += 8) {
#pragma unroll
            for (int jj = 0; jj < 8; jj++) {
                const int j = j0 + jj;
                int   s = __shfl_sync(0xffffffffu, sj, j);
                float w = __shfl_sync(0xffffffffu, ej, j);
                uint2 hv = *(const uint2*)&g_h2h[(size_t)s * 128 + lane * 4];
                float2 fa = __half22float2(*(const __half2*)&hv.x);
                float2 fb = __half22float2(*(const __half2*)&hv.y);
                den += w;
                acc[0] += w * fa.x; acc[1] += w * fa.y;
                acc[2] += w * fb.x; acc[3] += w * fb.y;
            }
        }
    }
    const float inv = 1.f / den;
    const float4 bv = *(const float4*)&b2[lane * 4];
    float o0 = eluf(acc[0] * inv + bv.x), o1 = eluf(acc[1] * inv + bv.y);
    float o2 = eluf(acc[2] * inv + bv.z), o3 = eluf(acc[3] * inv + bv.w);
    bf16 h0, l0, h1, l1, h2, l2, h3, l3;
    split_bf16(o0, h0, l0); split_bf16(o1, h1, l1);
    split_bf16(o2, h2, l2); split_bf16(o3, h3, l3);
    __nv_bfloat162 hpA, hpB, lpA, lpB;
    hpA.x = h0; hpA.y = h1; hpB.x = h2; hpB.y = h3;
    lpA.x = l0; lpA.y = l1; lpB.x = l2; lpB.y = l3;
    const size_t rb = (size_t)n * 256;
    *(__nv_bfloat162*)&g_tp[rb + lane * 4]           = hpA;
    *(__nv_bfloat162*)&g_tp[rb + lane * 4 + 2]       = hpB;
    *(__nv_bfloat162*)&g_tp[rb + 128 + lane * 4]     = lpA;
    *(__nv_bfloat162*)&g_tp[rb + 128 + lane * 4 + 2] = lpB;
}

// ================= 128-wide mma GEMM body, 4-stage pipeline =================
template <int ACT, int ATT>
__device__ __forceinline__ void mgemm_body(
    const bf16* __restrict__ Ap, const bf16* __restrict__ Bp,
    int K, int apitch, int bpitch, int Nn, int Wtot,
    const float* __restrict__ bias,
    float* __restrict__ Cf, __half* __restrict__ Ch, bf16* __restrict__ Cb2,
    const float* __restrict__ a_s, const float* __restrict__ a_d,
    float* __restrict__ atts, float* __restrict__ attd,
    int heads, int head, int row0, int col0, char* dyn)
{
    __shared__ float s_as[128], s_ad[128];
    const uint32_t dynu = smem_u32(dyn);

    const int tid = threadIdx.x;
    const int wid = tid >> 5, lane = tid & 31;
    const int g = lane >> 2, tig = lane & 3;
    const int warp_m = wid & 3, warp_n = wid >> 2;

    const int lrow = tid >> 1, lsel = tid & 1;
    const bf16* Agb = Ap + (size_t)(row0 + lrow) * apitch + lsel * K;
    const bf16* Bgb = Bp + (size_t)(col0 + lrow) * bpitch + lsel * K;
    const uint32_t soff = (uint32_t)lrow * 80u + (uint32_t)lsel * 32u;

    const int arow_l = (((lane >> 3) & 1) << 3) + (lane & 7);
    const int acol_l = (lane >> 4) << 3;
    const int brow_l = (lane & 7) + ((lane >> 4) << 3);
    const int bcol_l = ((lane >> 3) & 1) << 3;

    float c[2][8][4];
#pragma unroll
    for (int i = 0; i < 2; i++)
#pragma unroll
        for (int j = 0; j < 8; j++)
#pragma unroll
            for (int q = 0; q < 4; q++) c[i][j][q] = 0.f;

    const int NT = K >> 4;
#pragma unroll
    for (int p = 0; p < 3; p++) {
        if (p < NT) {
            const uint32_t st = dynu + (uint32_t)p * 20480u;
            const int koff = p * 16;
            cp_async16(st + soff, Agb + koff);
            cp_async16(st + soff + 16, Agb + koff + 8);
            cp_async16(st + 10240u + soff, Bgb + koff);
            cp_async16(st + 10240u + soff + 16, Bgb + koff + 8);
        }
        asm volatile("cp.async.commit_group;" ::: "memory");
    }

    for (int kt = 0; kt < NT; kt++) {
        const int rem = NT - 1 - kt;
        if (rem >= 2)      asm volatile("cp.async.wait_group 2;" ::: "memory");
        else if (rem == 1) asm volatile("cp.async.wait_group 1;" ::: "memory");
        else               asm volatile("cp.async.wait_group 0;" ::: "memory");
        __syncthreads();
        if (kt + 3 < NT) {
            const uint32_t st = dynu + (uint32_t)((kt + 3) & 3) * 20480u;
            const int koff = (kt + 3) * 16;
            cp_async16(st + soff, Agb + koff);
            cp_async16(st + soff + 16, Agb + koff + 8);
            cp_async16(st + 10240u + soff, Bgb + koff);
            cp_async16(st + 10240u + soff + 16, Bgb + koff + 8);
            asm volatile("cp.async.commit_group;" ::: "memory");
        }

        const uint32_t aBase = dynu + (uint32_t)(kt & 3) * 20480u;
        const uint32_t bBase = aBase + 10240u;

        uint32_t ah[2][4], al[2][4], bb[8][2];
#pragma unroll
        for (int mi = 0; mi < 2; mi++) {
            uint32_t r = aBase + (uint32_t)(warp_m * 32 + mi * 16 + arow_l) * 80u
                               + (uint32_t)acol_l * 2u;
            ldm_x4(ah[mi], r);
            ldm_x4(al[mi], r + 32u);
        }
#pragma unroll
        for (int p = 0; p < 4; p++) {
            uint32_t t[4];
            uint32_t r = bBase + (uint32_t)(warp_n * 64 + p * 16 + brow_l) * 80u
                               + (uint32_t)bcol_l * 2u;
            ldm_x4(t, r);
            bb[2 * p][0] = t[0]; bb[2 * p][1] = t[1];
            bb[2 * p + 1][0] = t[2]; bb[2 * p + 1][1] = t[3];
        }
#pragma unroll
        for (int mi = 0; mi < 2; mi++)
#pragma unroll
            for (int ni = 0; ni < 8; ni++)
                mma_bf16(c[mi][ni], ah[mi], bb[ni]);
#pragma unroll
        for (int mi = 0; mi < 2; mi++)
#pragma unroll
            for (int ni = 0; ni < 8; ni++)
                mma_bf16(c[mi][ni], al[mi], bb[ni]);
#pragma unroll
        for (int p = 0; p < 4; p++) {
            uint32_t t[4];
            uint32_t r = bBase + (uint32_t)(warp_n * 64 + p * 16 + brow_l) * 80u
                               + (uint32_t)bcol_l * 2u + 32u;
            ldm_x4(t, r);
            bb[2 * p][0] = t[0]; bb[2 * p][1] = t[1];
            bb[2 * p + 1][0] = t[2]; bb[2 * p + 1][1] = t[3];
        }
#pragma unroll
        for (int mi = 0; mi < 2; mi++)
#pragma unroll
            for (int ni = 0; ni < 8; ni++)
                mma_bf16(c[mi][ni], ah[mi], bb[ni]);
    }

    if (ATT) {
        __syncthreads();
        if (tid < 128) { s_as[tid] = 0.f; s_ad[tid] = 0.f; }
        __syncthreads();
    }

    float ssv[2][2] = {{0.f, 0.f}, {0.f, 0.f}};
    float sdv[2][2] = {{0.f, 0.f}, {0.f, 0.f}};

#pragma unroll
    for (int ni = 0; ni < 8; ni++) {
        const int cA = col0 + warp_n * 64 + ni * 8 + tig * 2;
        float b0 = 0.f, b1 = 0.f;
        if (bias) { b0 = __ldg(&bias[cA]); b1 = __ldg(&bias[cA + 1]); }
        float asA = 0.f, asB = 0.f, adA = 0.f, adB = 0.f;
        if (ATT) {
            asA = __ldg(&a_s[cA]); asB = __ldg(&a_s[cA + 1]);
            adA = __ldg(&a_d[cA]); adB = __ldg(&a_d[cA + 1]);
        }
#pragma unroll
        for (int mi = 0; mi < 2; mi++) {
            const int r0g = row0 + warp_m * 32 + mi * 16 + g;
            const int r1g = r0g + 8;
            float v00 = c[mi][ni][0] + b0, v01 = c[mi][ni][1] + b1;
            float v10 = c[mi][ni][2] + b0, v11 = c[mi][ni][3] + b1;
            if (ACT == 2) {
                v00 = eluf(v00); v01 = eluf(v01);
                v10 = eluf(v10); v11 = eluf(v11);
            }
            if (ATT) {
                ssv[mi][0] += v00 * asA + v01 * asB;
                ssv[mi][1] += v10 * asA + v11 * asB;
                sdv[mi][0] += v00 * adA + v01 * adB;
                sdv[mi][1] += v10 * adA + v11 * adB;
            }
            if (Cf) {
                *(float2*)&Cf[(size_t)r0g * Nn + cA] = make_float2(v00, v01);
                *(float2*)&Cf[(size_t)r1g * Nn + cA] = make_float2(v10, v11);
            }
            if (Ch) {
                *(__half2*)&Ch[(size_t)r0g * Nn + cA] = __floats2half2_rn(v00, v01);
                *(__half2*)&Ch[(size_t)r1g * Nn + cA] = __floats2half2_rn(v10, v11);
            }
            if (Cb2) {
                bf16 h0, l0, h1, l1;
                __nv_bfloat162 hp, lp;
                size_t rb0 = (size_t)r0g * 2 * Wtot;
                split_bf16(v00, h0, l0); split_bf16(v01, h1, l1);
                hp.x = h0; hp.y = h1; lp.x = l0; lp.y = l1;
                *(__nv_bfloat162*)&Cb2[rb0 + cA]        = hp;
                *(__nv_bfloat162*)&Cb2[rb0 + Wtot + cA] = lp;
                size_t rb1 = (size_t)r1g * 2 * Wtot;
                split_bf16(v10, h0, l0); split_bf16(v11, h1, l1);
                hp.x = h0; hp.y = h1; lp.x = l0; lp.y = l1;
                *(__nv_bfloat162*)&Cb2[rb1 + cA]        = hp;
                *(__nv_bfloat162*)&Cb2[rb1 + Wtot + cA] = lp;
            }
        }
    }

    if (ATT) {
#pragma unroll
        for (int mi = 0; mi < 2; mi++) {
            const int rl0 = warp_m * 32 + mi * 16 + g;
            atomicAdd(&s_as[rl0], ssv[mi][0]);
            atomicAdd(&s_as[rl0 + 8], ssv[mi][1]);
            atomicAdd(&s_ad[rl0], sdv[mi][0]);
            atomicAdd(&s_ad[rl0 + 8], sdv[mi][1]);
        }
        __syncthreads();
        if (tid < 128) {
            const int row = row0 + tid;
            atts[row * heads + head] = s_as[tid];
            attd[row * heads + head] = s_ad[tid];
        }
    }
}

__global__ void __launch_bounds__(256) k_gemmZ(const float* __restrict__ b1) {
    extern __shared__ char dyn[];
    const int head = blockIdx.x;
    mgemm_body<2, 0>(g_Zp + head * 256, g_W1t, 128, 1024, 256, 512, 512,
                     b1, nullptr, nullptr, g_e1p,
                     nullptr, nullptr, nullptr, nullptr,
                     1, 0, blockIdx.y * 128, head * 128, dyn);
}
__global__ void __launch_bounds__(256) k_mgemm2(const float* __restrict__ as2,
                                                const float* __restrict__ ad2) {
    extern __shared__ char dyn[];
    mgemm_body<0, 1>(g_e1p, g_W2t, 512, 1024, 1024, 128, 0,
                     nullptr, nullptr, g_h2h, nullptr,
                     as2, ad2, g_att2s, g_att2d,
                     1, 0, blockIdx.x * 128, 0, dyn);
}

// ================= fused node MLP (R13 config) =================
template <int AFROM>
__device__ __forceinline__ void gemm_stage(
    float (&c)[2][8][4],
    const bf16* Agb, const bf16* Bgb,
    uint32_t aChunkBase, uint32_t sAs, uint32_t sBs, uint32_t soff,
    int warp_m, int warp_n, int arow_l, int acol_l, int brow_l, int bcol_l)
{
#pragma unroll
    for (int i = 0; i < 2; i++)
#pragma unroll
        for (int j = 0; j < 8; j++)
#pragma unroll
            for (int q = 0; q < 4; q++) c[i][j][q] = 0.f;

    if (AFROM == 0) { cp_async16(sAs + soff, Agb); cp_async16(sAs + soff + 16, Agb + 8); }
    cp_async16(sBs + soff, Bgb);
    cp_async16(sBs + soff + 16, Bgb + 8);
    asm volatile("cp.async.commit_group;" ::: "memory");

#pragma unroll
    for (int kt = 0; kt < 8; kt++) {
        const int buf = kt & 1;
        if (kt + 1 < 8) {
            const int koff = (kt + 1) * 16;
            const uint32_t bofs = ((kt + 1) & 1) ? 10240u : 0u;
            if (AFROM == 0) {
                cp_async16(sAs + bofs + soff, Agb + koff);
                cp_async16(sAs + bofs + soff + 16, Agb + koff + 8);
            }
            cp_async16(sBs + bofs + soff, Bgb + koff);
            cp_async16(sBs + bofs + soff + 16, Bgb + koff + 8);
            asm volatile("cp.async.commit_group;" ::: "memory");
            asm volatile("cp.async.wait_group 1;" ::: "memory");
        } else {
            asm volatile("cp.async.wait_group 0;" ::: "memory");
        }
        __syncthreads();
        const uint32_t aBase = (AFROM == 0) ? (sAs + (uint32_t)buf * 10240u)
                                            : (aChunkBase + (uint32_t)kt * 10240u);
        const uint32_t bBase = sBs + (uint32_t)buf * 10240u;

        uint32_t ah[2][4], al[2][4], bb[8][2];
#pragma unroll
        for (int mi = 0; mi < 2; mi++) {
            uint32_t r = aBase + (uint32_t)(warp_m * 32 + mi * 16 + arow_l) * 80u
                               + (uint32_t)acol_l * 2u;
            ldm_x4(ah[mi], r);
            ldm_x4(al[mi], r + 32u);
        }
#pragma unroll
        for (int p = 0; p < 4; p++) {
            uint32_t t[4];
            uint32_t r = bBase + (uint32_t)(warp_n * 64 + p * 16 + brow_l) * 80u
                               + (uint32_t)bcol_l * 2u;
            ldm_x4(t, r);
            bb[2 * p][0] = t[0]; bb[2 * p][1] = t[1];
            bb[2 * p + 1][0] = t[2]; bb[2 * p + 1][1] = t[3];
        }
#pragma unroll
        for (int mi = 0; mi < 2; mi++)
#pragma unroll
            for (int ni = 0; ni < 8; ni++)
                mma_bf16(c[mi][ni], ah[mi], bb[ni]);
#pragma unroll
        for (int mi = 0; mi < 2; mi++)
#pragma unroll
            for (int ni = 0; ni < 8; ni++)
                mma_bf16(c[mi][ni], al[mi], bb[ni]);
#pragma unroll
        for (int p = 0; p < 4; p++) {
            uint32_t t[4];
            uint32_t r = bBase + (uint32_t)(warp_n * 64 + p * 16 + brow_l) * 80u
                               + (uint32_t)bcol_l * 2u + 32u;
            ldm_x4(t, r);
            bb[2 * p][0] = t[0]; bb[2 * p][1] = t[1];
            bb[2 * p + 1][0] = t[2]; bb[2 * p + 1][1] = t[3];
        }
#pragma unroll
        for (int mi = 0; mi < 2; mi++)
#pragma unroll
            for (int ni = 0; ni < 8; ni++)
                mma_bf16(c[mi][ni], ah[mi], bb[ni]);
        __syncthreads();
    }
}

__device__ __forceinline__ void store_split(char* base, int row, int col, float v0, float v1) {
    bf16 h0, l0, h1, l1;
    split_bf16(v0, h0, l0);
    split_bf16(v1, h1, l1);
    char* p = base + (col >> 4) * 10240 + row * 80 + (col & 15) * 2;
    __nv_bfloat162 hp, lp;
    hp.x = h0; hp.y = h1; lp.x = l0; lp.y = l1;
    *(__nv_bfloat162*)p = hp;
    *(__nv_bfloat162*)(p + 32) = lp;
}

__global__ void __launch_bounds__(256) k_nodeMLP(const float* __restrict__ bo1,
                                                 const float* __restrict__ bo2,
                                                 float* __restrict__ xo,
                                                 __half* __restrict__ PQh) {
    extern __shared__ char dyn[];
    char* uspC = dyn;
    char* xspC = dyn + 81920;
    const uint32_t dynu = smem_u32(dyn);
    const uint32_t uspU = dynu;
    const uint32_t xspU = dynu + 81920u;
    const uint32_t sAs  = dynu + 163840u;
    const uint32_t sBs  = dynu + 184320u;

    const int tid = threadIdx.x;
    const int wid = tid >> 5, lane = tid & 31;
    const int g = lane >> 2, tig = lane & 3;
    const int warp_m = wid & 3, warp_n = wid >> 2;
    const int row0 = blockIdx.x * 128;
    const int lrow = tid >> 1, lsel = tid & 1;
    const uint32_t soff = (uint32_t)lrow * 80u + (uint32_t)lsel * 32u;
    const int arow_l = (((lane >> 3) & 1) << 3) + (lane & 7);
    const int acol_l = (lane >> 4) << 3;
    const int brow_l = (lane & 7) + ((lane >> 4) << 3);
    const int bcol_l = ((lane >> 3) & 1) << 3;

    float c[2][8][4];

    {
        const bf16* Agb = g_tp + (size_t)(row0 + lrow) * 256 + lsel * 128;
        const bf16* Bgb = g_Wo1t + (size_t)lrow * 256 + lsel * 128;
        gemm_stage<0>(c, Agb, Bgb, 0u, sAs, sBs, soff,
                      warp_m, warp_n, arow_l, acol_l, brow_l, bcol_l);
#pragma unroll
        for (int ni = 0; ni < 8; ni++) {
            const int col = warp_n * 64 + ni * 8 + tig * 2;
            const float b0 = __ldg(&bo1[col]), b1 = __ldg(&bo1[col + 1]);
#pragma unroll
            for (int mi = 0; mi < 2; mi++) {
                const int r0l = warp_m * 32 + mi * 16 + g;
                store_split(uspC, r0l, col,
                            fmaxf(c[mi][ni][0] + b0, 0.f), fmaxf(c[mi][ni][1] + b1, 0.f));
                store_split(uspC, r0l + 8, col,
                            fmaxf(c[mi][ni][2] + b0, 0.f), fmaxf(c[mi][ni][3] + b1, 0.f));
            }
        }
        __syncthreads();
    }

    {
        const bf16* Bgb = g_Wo2t + (size_t)lrow * 256 + lsel * 128;
        gemm_stage<1>(c, nullptr, Bgb, uspU, sAs, sBs, soff,
                      warp_m, warp_n, arow_l, acol_l, brow_l, bcol_l);
#pragma unroll
        for (int ni = 0; ni < 8; ni++) {
            const int col = warp_n * 64 + ni * 8 + tig * 2;
            const float b0 = __ldg(&bo2[col]), b1 = __ldg(&bo2[col + 1]);
#pragma unroll
            for (int mi = 0; mi < 2; mi++) {
                const int r0l = warp_m * 32 + mi * 16 + g;
                const int r1l = r0l + 8;
                float v00 = c[mi][ni][0] + b0, v01 = c[mi][ni][1] + b1;
                float v10 = c[mi][ni][2] + b0, v11 = c[mi][ni][3] + b1;
                *(float2*)&xo[(size_t)(row0 + r0l) * 128 + col] = make_float2(v00, v01);
                *(float2*)&xo[(size_t)(row0 + r1l) * 128 + col] = make_float2(v10, v11);
                store_split(xspC, r0l, col, v00, v01);
                store_split(xspC, r1l, col, v10, v11);
            }
        }
        __syncthreads();
    }

#pragma unroll
    for (int p = 0; p < 2; p++) {
        const bf16* Bgb = g_WePQt + (size_t)(p * 128 + lrow) * 256 + lsel * 128;
        gemm_stage<1>(c, nullptr, Bgb, xspU, sAs, sBs, soff,
                      warp_m, warp_n, arow_l, acol_l, brow_l, bcol_l);
#pragma unroll
        for (int ni = 0; ni < 8; ni++) {
            const int col = warp_n * 64 + ni * 8 + tig * 2;
            const int gcol = p * 128 + col;
            const float b0 = g_bePQ[gcol], b1 = g_bePQ[gcol + 1];
#pragma unroll
            for (int mi = 0; mi < 2; mi++) {
                const int r0g = row0 + warp_m * 32 + mi * 16 + g;
                const int r1g = r0g + 8;
                *(__half2*)&PQh[(size_t)r0g * 256 + gcol] =
                    __floats2half2_rn(c[mi][ni][0] + b0, c[mi][ni][1] + b1);
                *(__half2*)&PQh[(size_t)r1g * 256 + gcol] =
                    __floats2half2_rn(c[mi][ni][2] + b0, c[mi][ni][3] + b1);
            }
        }
    }
}

// ================= edge MLP v3: 128 edges/block =================
__global__ void __launch_bounds__(256) k_edge_final(const void* __restrict__ ei,
                                                    const float* __restrict__ eattr,
                                                    const float* __restrict__ We1,
                                                    const float* __restrict__ We2,
                                                    const float* __restrict__ be2,
                                                    float* __restrict__ out) {
    __shared__ float  sW1f[16 * 128];
    __shared__ __half sHid[128][136];
    __shared__ __half sW2h[16][136];
    const int tid = threadIdx.x, wid = tid >> 5, lane = tid & 31;

    for (int i = tid; i < 2048; i += 256) {
        sW1f[i] = We1[256 * 128 + i];
        int cc = i >> 4, o = i & 15;
        sW2h[o][cc] = __float2half(We2[i]);
    }
    __syncthreads();

    float4 w1r[16];
#pragma unroll
    for (int k = 0; k < 16; k++) w1r[k] = *(const float4*)&sW1f[k * 128 + lane * 4];

    const int is64 = g_is64;
    const long e0 = (long)blockIdx.x * 128;

#pragma unroll
    for (int r = 0; r < 16; r++) {
        const long e = e0 + wid * 16 + r;
        int s = idx_at(ei, e, is64);
        int d = idx_at(ei, (long)EE + e, is64);
        uint2 pv = *(const uint2*)&g_PQh[(size_t)s * 256 + lane * 4];
        uint2 qv = *(const uint2*)&g_PQh[(size_t)d * 256 + 128 + lane * 4];
        float2 pa = __half22float2(*(const __half2*)&pv.x);
        float2 pb = __half22float2(*(const __half2*)&pv.y);
        float2 qa = __half22float2(*(const __half2*)&qv.x);
        float2 qb = __half22float2(*(const __half2*)&qv.y);
        float4 hv;
        hv.x = pa.x + qa.x; hv.y = pa.y + qa.y;
        hv.z = pb.x + qb.x; hv.w = pb.y + qb.y;
        float eav = (lane < 16) ? eattr[e * 16 + lane] : 0.f;
#pragma unroll
        for (int k = 0; k < 16; k++) {
            float ek = __shfl_sync(0xffffffffu, eav, k);
            hv.x += ek * w1r[k].x; hv.y += ek * w1r[k].y;
            hv.z += ek * w1r[k].z; hv.w += ek * w1r[k].w;
        }
        __half2 h01 = __floats2half2_rn(fmaxf(hv.x, 0.f), fmaxf(hv.y, 0.f));
        __half2 h23 = __floats2half2_rn(fmaxf(hv.z, 0.f), fmaxf(hv.w, 0.f));
        uint2 packed;
        packed.x = *(uint32_t*)&h01;
        packed.y = *(uint32_t*)&h23;
        *(uint2*)&sHid[wid * 16 + r][lane * 4] = packed;
    }
    __syncthreads();

    {
        const int g = lane >> 2, tig = lane & 3;
        const int arow_l = (((lane >> 3) & 1) << 3) + (lane & 7);
        const int acol_l = (lane >> 4) << 3;
        const int brow_l = (lane & 7) + ((lane >> 4) << 3);
        const int bcol_l = ((lane >> 3) & 1) << 3;
        const uint32_t sA = smem_u32(&sHid[wid * 16][0]);
        const uint32_t sB = smem_u32(&sW2h[0][0]);

        float c0[4] = {0.f, 0.f, 0.f, 0.f};
        float c1[4] = {0.f, 0.f, 0.f, 0.f};
#pragma unroll
        for (int kk = 0; kk < 128; kk += 16) {
            uint32_t af[4], bfr[4];
            ldm_x4(af, sA + (uint32_t)arow_l * 272u + (uint32_t)(kk + acol_l) * 2u);
            ldm_x4(bfr, sB + (uint32_t)brow_l * 272u + (uint32_t)(kk + bcol_l) * 2u);
            mma_f16(c0, af, bfr);
            mma_f16(c1, af, bfr + 2);
        }

        const long eA = e0 + wid * 16 + g;
        const long eB = eA + 8;
        const float b0 = __ldg(&be2[tig * 2]),     b1 = __ldg(&be2[tig * 2 + 1]);
        const float b8 = __ldg(&be2[8 + tig * 2]), b9 = __ldg(&be2[8 + tig * 2 + 1]);
        *(float2*)&out[eA * 16 + tig * 2]     = make_float2(c0[0] + b0, c0[1] + b1);
        *(float2*)&out[eB * 16 + tig * 2]     = make_float2(c0[2] + b0, c0[3] + b1);
        *(float2*)&out[eA * 16 + 8 + tig * 2] = make_float2(c1[0] + b8, c1[1] + b9);
        *(float2*)&out[eB * 16 + 8 + tig * 2] = make_float2(c1[2] + b8, c1[3] + b9);
    }
}

// ================= launcher =================
extern "C" void kernel_launch(void* const* d_in, const int* in_sizes, int n_in,
                              void* d_out, int out_size) {
    const float* x    = (const float*)d_in[0];
    const void*  ei   = d_in[1];
    const float* eatt = (const float*)d_in[2];
    const float* W1   = (const float*)d_in[3];
    const float* as1  = (const float*)d_in[4];
    const float* ad1  = (const float*)d_in[5];
    const float* b1   = (const float*)d_in[6];
    const float* W2   = (const float*)d_in[7];
    const float* as2  = (const float*)d_in[8];
    const float* ad2  = (const float*)d_in[9];
    const float* b2   = (const float*)d_in[10];
    const float* Wo1  = (const float*)d_in[11];
    const float* bo1  = (const float*)d_in[12];
    const float* Wo2  = (const float*)d_in[13];
    const float* bo2  = (const float*)d_in[14];
    const float* We1  = (const float*)d_in[15];
    const float* be1  = (const float*)d_in[16];
    const float* We2  = (const float*)d_in[17];
    const float* be2  = (const float*)d_in[18];

    float* out  = (float*)d_out;
    float* xo   = out;
    float* eout = out + (size_t)NN * 128;

    __half* PQh;
    cudaGetSymbolAddress((void**)&PQh, g_PQh);

    cudaFuncSetAttribute(k_gemmZ, cudaFuncAttributeMaxDynamicSharedMemorySize, 81920);
    cudaFuncSetAttribute(k_mgemm2, cudaFuncAttributeMaxDynamicSharedMemorySize, 81920);
    cudaFuncSetAttribute(k_nodeMLP, cudaFuncAttributeMaxDynamicSharedMemorySize, 204800);

    // 0: prep = xh (vectorized) | convW | init | va
    k_prep<<<4899, 256>>>(x, (const int*)ei, W1, W2, Wo1, Wo2, We1, be1, as1, ad1);
    // 1: hist (4 edges/thread) | attdot
    k_histdot<<<HBLK + 4000, 256>>>(ei);
    // 2: scan
    k_scan_all<<<1, 1024>>>();
    // 3: scatter (4 edges/thread, profiled slot)
    k_scatter<<<HBLK, 256>>>(ei);
    // 4: agg1x
    k_agg1x<<<4000, 256>>>();
    // 5: gemmZ
    k_gemmZ<<<dim3(4, 250), 256, 81920>>>(b1);
    // 6: gemm2
    k_mgemm2<<<250, 256, 81920>>>(as2, ad2);
    // 7: agg2
    k_agg2<<<4000, 256>>>(b2);
    // 8: node MLP
    k_nodeMLP<<<250, 256, 204800>>>(bo1, bo2, xo, PQh);
    // 9: edge MLP v3
    k_edge_final<<<EE / 128, 256>>>(ei, eatt, We1, We2, be2, eout);
}